// round 14
// baseline (speedup 1.0000x reference)
#include <cuda_runtime.h>
#include <cuda_fp16.h>
#include <math.h>

#define N_TOK 16384
#define DIM   512
#define NH    8
#define DH    64
#define NC    512
#define QKVW  1536
#define KW    33

__device__ float  g_qkv [(long)N_TOK*QKVW];
__device__ float  g_a2  [NH*NC*NC];
__device__ __half g_a2h [NH*NC*NC];
__device__ __half g_xz  [NH*NC*NC];
__device__ __half g_u1  [NH*NC*NC];
__device__ __half g_u2  [NH*NC*NC];
__device__ __half g_za  [NH*NC*NC];
__device__ __half g_zb  [NH*NC*NC];
__device__ float  g_ql  [NH*NC*DH];
__device__ float  g_kl  [NH*NC*DH];
__device__ float  g_a3v [NH*NC*DH];
__device__ float  g_wm  [NH*NC*DH];
__device__ float  g_osort[(long)N_TOK*DIM];
__device__ int    g_idx [N_TOK];
__device__ int    g_counts [NC];
__device__ int    g_offsets[NC];
__device__ int    g_bh[64*NC];
__device__ unsigned g_maxcs;
__device__ unsigned g_bar;

__device__ __forceinline__ unsigned f2tf32(float v) {
    unsigned r; asm("cvt.rna.tf32.f32 %0, %1;" : "=r"(r) : "f"(v)); return r;
}
__device__ __forceinline__ void mma_tf32(float* c, const unsigned* a, const unsigned* b) {
    asm volatile("mma.sync.aligned.m16n8k8.row.col.f32.tf32.tf32.f32 "
        "{%0,%1,%2,%3}, {%4,%5,%6,%7}, {%8,%9}, {%0,%1,%2,%3};"
        : "+f"(c[0]), "+f"(c[1]), "+f"(c[2]), "+f"(c[3])
        : "r"(a[0]), "r"(a[1]), "r"(a[2]), "r"(a[3]), "r"(b[0]), "r"(b[1]));
}
__device__ __forceinline__ unsigned f2h2(float a, float b) {
    __half2 h = __floats2half2_rn(a, b);
    return *(unsigned*)&h;
}
__device__ __forceinline__ void mma_f16(float* c, const unsigned* a, const unsigned* b) {
    asm volatile("mma.sync.aligned.m16n8k16.row.col.f32.f16.f16.f32 "
        "{%0,%1,%2,%3}, {%4,%5,%6,%7}, {%8,%9}, {%0,%1,%2,%3};"
        : "+f"(c[0]), "+f"(c[1]), "+f"(c[2]), "+f"(c[3])
        : "r"(a[0]), "r"(a[1]), "r"(a[2]), "r"(a[3]), "r"(b[0]), "r"(b[1]));
}

// ============ tt_gemm (fp32 in, fp16 MMA): 128x128 tile, 256 thr, K-chunk 32 ============
template<bool TB, bool SCAT>
__global__ void __launch_bounds__(256) tt_gemm(
    const float* __restrict__ A, int lda, long sA,
    const float* __restrict__ B, int ldb, long sB,
    float* __restrict__ C, int ldc, long sC,
    int K, float alpha,
    const int* __restrict__ gatherA, const int* __restrict__ scatterC,
    const float* __restrict__ bias)
{
    __shared__ unsigned As[2][128][20];
    __shared__ unsigned Bs[2][16][132];
    int h = blockIdx.z;
    A += (long)h * sA; B += (long)h * sB; C += (long)h * sC;
    int bm = blockIdx.y * 128, bn = blockIdx.x * 128;
    int tid = threadIdx.x, lane = tid & 31, wid = tid >> 5;
    int warpM = wid >> 1, warpN = wid & 1, g = lane >> 2, tg = lane & 3;

    int ar = tid >> 1, akb = (tid & 1) * 16;
    int grow = bm + ar;
    if (gatherA) grow = gatherA[grow];
    const float* Ap = A + (long)grow * lda + akb;

    const float* Bp;
    int bsn = 0, bsk = 0, bp2 = 0;
    if (TB) { bsn = tid >> 1; bsk = (tid & 1) * 16;
              Bp = B + (long)(bn + bsn) * ldb + bsk; }
    else    { bp2 = tid >> 4; bsn = (tid & 15) * 8;
              Bp = B + (long)(2 * bp2) * ldb + bn + bsn; }

    float aR[16], bR[16];
    float acc[2][8][4];
    #pragma unroll
    for (int i = 0; i < 2; i++)
        #pragma unroll
        for (int j = 0; j < 8; j++)
            #pragma unroll
            for (int l = 0; l < 4; l++) acc[i][j][l] = 0.f;

    #define TLDG(k0) do {                                                      \
        float4 _a0 = *(const float4*)(Ap + (k0));                              \
        float4 _a1 = *(const float4*)(Ap + (k0) + 4);                          \
        float4 _a2 = *(const float4*)(Ap + (k0) + 8);                          \
        float4 _a3 = *(const float4*)(Ap + (k0) + 12);                         \
        aR[0]=_a0.x; aR[1]=_a0.y; aR[2]=_a0.z; aR[3]=_a0.w;                    \
        aR[4]=_a1.x; aR[5]=_a1.y; aR[6]=_a1.z; aR[7]=_a1.w;                    \
        aR[8]=_a2.x; aR[9]=_a2.y; aR[10]=_a2.z; aR[11]=_a2.w;                  \
        aR[12]=_a3.x; aR[13]=_a3.y; aR[14]=_a3.z; aR[15]=_a3.w;                \
        if (TB) {                                                              \
            float4 _b0 = *(const float4*)(Bp + (k0));                          \
            float4 _b1 = *(const float4*)(Bp + (k0) + 4);                      \
            float4 _b2 = *(const float4*)(Bp + (k0) + 8);                      \
            float4 _b3 = *(const float4*)(Bp + (k0) + 12);                     \
            bR[0]=_b0.x; bR[1]=_b0.y; bR[2]=_b0.z; bR[3]=_b0.w;                \
            bR[4]=_b1.x; bR[5]=_b1.y; bR[6]=_b1.z; bR[7]=_b1.w;                \
            bR[8]=_b2.x; bR[9]=_b2.y; bR[10]=_b2.z; bR[11]=_b2.w;              \
            bR[12]=_b3.x; bR[13]=_b3.y; bR[14]=_b3.z; bR[15]=_b3.w;            \
        } else {                                                               \
            const float* _r0 = Bp + (long)(k0) * ldb;                          \
            const float* _r1 = _r0 + ldb;                                      \
            float4 _x0 = *(const float4*)(_r0);                                \
            float4 _x1 = *(const float4*)(_r0 + 4);                            \
            float4 _y0 = *(const float4*)(_r1);                                \
            float4 _y1 = *(const float4*)(_r1 + 4);                            \
            bR[0]=_x0.x; bR[1]=_x0.y; bR[2]=_x0.z; bR[3]=_x0.w;                \
            bR[4]=_x1.x; bR[5]=_x1.y; bR[6]=_x1.z; bR[7]=_x1.w;                \
            bR[8]=_y0.x; bR[9]=_y0.y; bR[10]=_y0.z; bR[11]=_y0.w;              \
            bR[12]=_y1.x; bR[13]=_y1.y; bR[14]=_y1.z; bR[15]=_y1.w;            \
        }                                                                      \
    } while (0)

    #define TST(p) do {                                                        \
        int _cb = (tid & 1) * 8;                                               \
        _Pragma("unroll")                                                      \
        for (int _j = 0; _j < 4; _j++)                                         \
            *(uint2*)&As[p][ar][_cb + 2 * _j] = make_uint2(                    \
                f2h2(aR[2*_j], aR[2*_j+1]), f2h2(aR[2*_j+8], aR[2*_j+9]));     \
        if (TB) {                                                              \
            int _kb2 = (tid & 1) * 8, _s = (bsn & 7) * 16 + (bsn >> 3);        \
            _Pragma("unroll")                                                  \
            for (int _j = 0; _j < 8; _j++)                                     \
                Bs[p][_kb2 + _j][_s] = f2h2(bR[2*_j], bR[2*_j+1]);             \
        } else {                                                               \
            int _t = tid & 15;                                                 \
            _Pragma("unroll")                                                  \
            for (int _j = 0; _j < 8; _j++)                                     \
                Bs[p][bp2][_j * 16 + _t] = f2h2(bR[_j], bR[8 + _j]);           \
        }                                                                      \
    } while (0)

    TLDG(0); TST(0);
    __syncthreads();
    int buf = 0;
    for (int k0 = 0; k0 < K; k0 += 32) {
        bool nxt = (k0 + 32) < K;
        if (nxt) TLDG(k0 + 32);
        #pragma unroll
        for (int c = 0; c < 2; c++) {
            unsigned af[2][4];
            #pragma unroll
            for (int mt = 0; mt < 2; mt++) {
                int r0 = warpM * 32 + mt * 16;
                uint2 p0 = *(const uint2*)&As[buf][r0 + g    ][c * 8 + 2 * tg];
                uint2 p1 = *(const uint2*)&As[buf][r0 + g + 8][c * 8 + 2 * tg];
                af[mt][0] = p0.x; af[mt][1] = p1.x; af[mt][2] = p0.y; af[mt][3] = p1.y;
            }
            unsigned bf[8][2];
            {
                int s0 = g * 16 + warpN * 8;
                uint4 q0 = *(const uint4*)&Bs[buf][c * 8 + tg    ][s0];
                uint4 q1 = *(const uint4*)&Bs[buf][c * 8 + tg    ][s0 + 4];
                uint4 q2 = *(const uint4*)&Bs[buf][c * 8 + tg + 4][s0];
                uint4 q3 = *(const uint4*)&Bs[buf][c * 8 + tg + 4][s0 + 4];
                bf[0][0]=q0.x; bf[1][0]=q0.y; bf[2][0]=q0.z; bf[3][0]=q0.w;
                bf[4][0]=q1.x; bf[5][0]=q1.y; bf[6][0]=q1.z; bf[7][0]=q1.w;
                bf[0][1]=q2.x; bf[1][1]=q2.y; bf[2][1]=q2.z; bf[3][1]=q2.w;
                bf[4][1]=q3.x; bf[5][1]=q3.y; bf[6][1]=q3.z; bf[7][1]=q3.w;
            }
            #pragma unroll
            for (int mt = 0; mt < 2; mt++)
                #pragma unroll
                for (int nt = 0; nt < 8; nt++)
                    mma_f16(acc[mt][nt], af[mt], bf[nt]);
        }
        if (nxt) { TST(buf ^ 1); __syncthreads(); }
        buf ^= 1;
    }

    #pragma unroll
    for (int mt = 0; mt < 2; mt++) {
        int r0 = bm + warpM * 32 + mt * 16 + g, r1 = r0 + 8;
        int sr0 = SCAT ? scatterC[r0] : r0;
        int sr1 = SCAT ? scatterC[r1] : r1;
        #pragma unroll
        for (int nt = 0; nt < 8; nt++) {
            int col = bn + warpN * 64 + nt * 8 + 2 * tg;
            float v0 = alpha * acc[mt][nt][0], v1 = alpha * acc[mt][nt][1];
            float v2 = alpha * acc[mt][nt][2], v3 = alpha * acc[mt][nt][3];
            if (bias) {
                float b0 = bias[col], b1 = bias[col + 1];
                v0 += b0; v1 += b1; v2 += b0; v3 += b1;
            }
            *(float2*)&C[(long)sr0 * ldc + col] = make_float2(v0, v1);
            *(float2*)&C[(long)sr1 * ldc + col] = make_float2(v2, v3);
        }
    }
    #undef TLDG
    #undef TST
}

// ============ fused pinv megakernel: 24 GEMM stages, grid barrier ============
template<bool DIAG>
__device__ __forceinline__ void pinv_tile(
    const __half* __restrict__ A, const __half* __restrict__ B, __half* __restrict__ C,
    float alpha, float diagc, int bm, int bn,
    unsigned As[2][128][20], unsigned Bs[2][16][132])
{
    int tid = threadIdx.x, lane = tid & 31, wid = tid >> 5;
    int warpM = wid >> 1, warpN = wid & 1, g = lane >> 2, tg = lane & 3;
    int ar = tid >> 1, akb = (tid & 1) * 16;
    const __half* Ap = A + (long)(bm + ar) * NC + akb;
    int bp2 = tid >> 4, bsn = (tid & 15) * 8;
    const __half* Bp = B + (long)(2 * bp2) * NC + bn + bsn;
    __half dch = __float2half(diagc), zh = __float2half(0.f);

    unsigned aU[8], bU[8];
    float acc[2][8][4];
    #pragma unroll
    for (int i = 0; i < 2; i++)
        #pragma unroll
        for (int j = 0; j < 8; j++)
            #pragma unroll
            for (int l = 0; l < 4; l++) acc[i][j][l] = 0.f;

    #define HLDG(k0) do {                                                      \
        uint4 _a01 = __ldcg((const uint4*)(Ap + (k0)));                        \
        uint4 _a23 = __ldcg((const uint4*)(Ap + (k0) + 8));                    \
        aU[0]=_a01.x; aU[1]=_a01.y; aU[2]=_a01.z; aU[3]=_a01.w;                \
        aU[4]=_a23.x; aU[5]=_a23.y; aU[6]=_a23.z; aU[7]=_a23.w;                \
        uint4 _r0 = __ldcg((const uint4*)(Bp + (long)(k0) * NC));              \
        uint4 _r1 = __ldcg((const uint4*)(Bp + (long)(k0) * NC + NC));         \
        const unsigned short* _h0 = (const unsigned short*)&_r0;               \
        const unsigned short* _h1 = (const unsigned short*)&_r1;               \
        _Pragma("unroll")                                                      \
        for (int _j = 0; _j < 8; _j++)                                         \
            bU[_j] = (unsigned)_h0[_j] | ((unsigned)_h1[_j] << 16);            \
        if (DIAG) {                                                            \
            int _ka = (k0) + 2 * bp2, _kb = _ka + 1, _n = bn + bsn;            \
            _Pragma("unroll")                                                  \
            for (int _j = 0; _j < 8; _j++) {                                   \
                __half2 _d = __halves2half2((_ka == _n + _j) ? dch : zh,       \
                                            (_kb == _n + _j) ? dch : zh);      \
                __half2 _b = *(__half2*)&bU[_j];                               \
                __half2 _o = __hsub2(_d, _b);                                  \
                bU[_j] = *(unsigned*)&_o;                                      \
            }                                                                  \
        }                                                                      \
    } while (0)

    #define HST(p) do {                                                        \
        int _cb = (tid & 1) * 8;                                               \
        _Pragma("unroll")                                                      \
        for (int _j = 0; _j < 4; _j++)                                         \
            *(uint2*)&As[p][ar][_cb + 2 * _j] = make_uint2(aU[_j], aU[_j + 4]);\
        int _t = tid & 15;                                                     \
        _Pragma("unroll")                                                      \
        for (int _j = 0; _j < 8; _j++)                                         \
            Bs[p][bp2][_j * 16 + _t] = bU[_j];                                 \
    } while (0)

    HLDG(0); HST(0);
    __syncthreads();
    int buf = 0;
    for (int k0 = 0; k0 < NC; k0 += 32) {
        bool nxt = (k0 + 32) < NC;
        if (nxt) HLDG(k0 + 32);
        #pragma unroll
        for (int c = 0; c < 2; c++) {
            unsigned af[2][4];
            #pragma unroll
            for (int mt = 0; mt < 2; mt++) {
                int r0 = warpM * 32 + mt * 16;
                uint2 p0 = *(const uint2*)&As[buf][r0 + g    ][c * 8 + 2 * tg];
                uint2 p1 = *(const uint2*)&As[buf][r0 + g + 8][c * 8 + 2 * tg];
                af[mt][0] = p0.x; af[mt][1] = p1.x; af[mt][2] = p0.y; af[mt][3] = p1.y;
            }
            unsigned bf[8][2];
            {
                int s0 = g * 16 + warpN * 8;
                uint4 q0 = *(const uint4*)&Bs[buf][c * 8 + tg    ][s0];
                uint4 q1 = *(const uint4*)&Bs[buf][c * 8 + tg    ][s0 + 4];
                uint4 q2 = *(const uint4*)&Bs[buf][c * 8 + tg + 4][s0];
                uint4 q3 = *(const uint4*)&Bs[buf][c * 8 + tg + 4][s0 + 4];
                bf[0][0]=q0.x; bf[1][0]=q0.y; bf[2][0]=q0.z; bf[3][0]=q0.w;
                bf[4][0]=q1.x; bf[5][0]=q1.y; bf[6][0]=q1.z; bf[7][0]=q1.w;
                bf[0][1]=q2.x; bf[1][1]=q2.y; bf[2][1]=q2.z; bf[3][1]=q2.w;
                bf[4][1]=q3.x; bf[5][1]=q3.y; bf[6][1]=q3.z; bf[7][1]=q3.w;
            }
            #pragma unroll
            for (int mt = 0; mt < 2; mt++)
                #pragma unroll
                for (int nt = 0; nt < 8; nt++)
                    mma_f16(acc[mt][nt], af[mt], bf[nt]);
        }
        if (nxt) { HST(buf ^ 1); __syncthreads(); }
        buf ^= 1;
    }

    #pragma unroll
    for (int mt = 0; mt < 2; mt++) {
        int r0 = bm + warpM * 32 + mt * 16 + g, r1 = r0 + 8;
        #pragma unroll
        for (int nt = 0; nt < 8; nt++) {
            int col = bn + warpN * 64 + nt * 8 + 2 * tg;
            __stcg((unsigned*)&C[(long)r0 * NC + col],
                   f2h2(alpha * acc[mt][nt][0], alpha * acc[mt][nt][1]));
            __stcg((unsigned*)&C[(long)r1 * NC + col],
                   f2h2(alpha * acc[mt][nt][2], alpha * acc[mt][nt][3]));
        }
    }
    #undef HLDG
    #undef HST
}

__global__ void __launch_bounds__(256) pinv_fused_kernel(
    const __half* __restrict__ a2h, __half* __restrict__ xz,
    __half* __restrict__ u1, __half* __restrict__ u2,
    __half* __restrict__ za, __half* __restrict__ zb)
{
    __shared__ unsigned As[2][128][20];
    __shared__ unsigned Bs[2][16][132];
    int bid = blockIdx.x;
    int h = bid >> 4, by = (bid >> 2) & 3, bx = bid & 3;
    int bm = by * 128, bn = bx * 128;
    long off = (long)h * NC * NC;
    unsigned epoch = 0;

    #define GRID_BAR() do {                                                    \
        __threadfence();                                                       \
        __syncthreads();                                                       \
        if (threadIdx.x == 0) {                                                \
            atomicAdd(&g_bar, 1u);                                             \
            epoch += 128;                                                      \
            while (*(volatile unsigned*)&g_bar < epoch) { }                    \
            __threadfence();                                                   \
        }                                                                      \
        __syncthreads();                                                       \
    } while (0)

    __half* zc = za; __half* zn = zb;
    for (int it = 0; it < 6; it++) {
        pinv_tile<false>(a2h + off, zc + off, xz + off, 1.f, 0.f, bm, bn, As, Bs);
        GRID_BAR();
        pinv_tile<true >(xz + off, xz + off, u1 + off, 1.f, 7.f, bm, bn, As, Bs);
        GRID_BAR();
        pinv_tile<true >(xz + off, u1 + off, u2 + off, 1.f, 15.f, bm, bn, As, Bs);
        GRID_BAR();
        pinv_tile<true >(zc + off, u2 + off, zn + off, 0.25f, 13.f, bm, bn, As, Bs);
        GRID_BAR();
        __half* t = zc; zc = zn; zn = t;
    }
    #undef GRID_BAR
}

// ---------------- sort ----------------
__global__ void init_scalars_kernel() { g_maxcs = 0u; }

__global__ void hist_kernel(const int* __restrict__ labels) {
    __shared__ int sh[NC];
    int t = threadIdx.x;
    sh[t] = 0; sh[t + 256] = 0;
    __syncthreads();
    atomicAdd(&sh[labels[blockIdx.x * 256 + t]], 1);
    __syncthreads();
    g_bh[blockIdx.x * NC + t]       = sh[t];
    g_bh[blockIdx.x * NC + t + 256] = sh[t + 256];
}

__global__ void scan_kernel() {
    __shared__ int s[NC];
    int c = threadIdx.x;
    int tot = 0;
    for (int b = 0; b < 64; b++) { int v = g_bh[b * NC + c]; g_bh[b * NC + c] = tot; tot += v; }
    g_counts[c] = tot; s[c] = tot;
    __syncthreads();
    for (int d = 1; d < NC; d <<= 1) {
        int v = (c >= d) ? s[c - d] : 0;
        __syncthreads(); s[c] += v; __syncthreads();
    }
    int excl = s[c] - tot;
    g_offsets[c] = excl;
    for (int b = 0; b < 64; b++) g_bh[b * NC + c] += excl;
}

__global__ void place_kernel(const int* __restrict__ labels) {
    __shared__ int slab[256];
    int t = threadIdx.x, i = blockIdx.x * 256 + t;
    int c = labels[i];
    slab[t] = c;
    __syncthreads();
    int rank = 0;
    for (int j = 0; j < t; j++) rank += (slab[j] == c);
    g_idx[g_bh[blockIdx.x * NC + c] + rank] = i;
}

__global__ void landmark_kernel() {
    int c = blockIdx.x, h = blockIdx.y, t = threadIdx.x;
    int start = g_offsets[c], cnt = g_counts[c];
    int col = (t < DH) ? (h * DH + t) : (DIM + h * DH + (t - DH));
    float s = 0.f;
    for (int r = 0; r < cnt; r++) s += g_qkv[(long)(start + r) * QKVW + col];
    float m = s / (float)(cnt > 0 ? cnt : 1);
    long o = ((long)h * NC + c) * DH;
    if (t < DH) g_ql[o + t] = m; else g_kl[o + (t - DH)] = m;
}

__global__ void softmax_kernel(float* __restrict__ d, int C) {
    d += blockIdx.x * (long)C;
    __shared__ float red[256];
    int t = threadIdx.x;
    float m = -1e30f;
    for (int i = t; i < C; i += 256) m = fmaxf(m, d[i]);
    red[t] = m; __syncthreads();
    for (int s = 128; s > 0; s >>= 1) { if (t < s) red[t] = fmaxf(red[t], red[t + s]); __syncthreads(); }
    m = red[0]; __syncthreads();
    float sum = 0.f;
    for (int i = t; i < C; i += 256) { float e = expf(d[i] - m); d[i] = e; sum += e; }
    red[t] = sum; __syncthreads();
    for (int s = 128; s > 0; s >>= 1) { if (t < s) red[t] += red[t + s]; __syncthreads(); }
    float inv = 1.f / red[0];
    for (int i = t; i < C; i += 256) d[i] *= inv;
}

__global__ void colsum_kernel() {
    int h = blockIdx.x, t = threadIdx.x;
    const float* d = g_a2 + (long)h * NC * NC;
    float s0 = 0.f, s1 = 0.f, s2 = 0.f, s3 = 0.f;
    #pragma unroll 4
    for (int r = 0; r < NC; r += 4) {
        s0 += d[(long)r * NC + t];
        s1 += d[(long)(r + 1) * NC + t];
        s2 += d[(long)(r + 2) * NC + t];
        s3 += d[(long)(r + 3) * NC + t];
    }
    float s = (s0 + s1) + (s2 + s3);
    __shared__ float red[512];
    red[t] = s; __syncthreads();
    for (int k = 256; k > 0; k >>= 1) { if (t < k) red[t] = fmaxf(red[t], red[t + k]); __syncthreads(); }
    if (t == 0) atomicMax(&g_maxcs, __float_as_uint(red[0]));
}

__global__ void zinit_kernel() {
    if (blockIdx.x == 0 && threadIdx.x == 0) g_bar = 0u;
    float scale = 1.f / __uint_as_float(g_maxcs);
    long id = (long)blockIdx.x * 256 + threadIdx.x;
    int j = (int)(id & 511), i = (int)((id >> 9) & 511);
    long h = id >> 18;
    g_za[id]  = __float2half(g_a2[(h << 18) + ((long)j << 9) + i] * scale);
    g_a2h[id] = __float2half(g_a2[id]);
}

// depthwise conv residual -> PURE STORE into osort (flash1 accumulates on top)
#define CTI 128
__global__ void conv_add_kernel(const float* __restrict__ w_res) {
    __shared__ float sv[CTI + KW - 1][DH];
    __shared__ float w[KW];
    int h = blockIdx.y, i0 = blockIdx.x * CTI, t = threadIdx.x;
    if (t < KW) w[t] = w_res[h * KW + t];
    for (int e = t; e < (CTI + KW - 1) * (DH / 2); e += 256) {
        int r = e >> 5, c2 = e & 31;
        int gi = i0 + r - KW / 2;
        float2 v = make_float2(0.f, 0.f);
        if (gi >= 0 && gi < N_TOK)
            v = *(const float2*)&g_qkv[(long)gi * QKVW + 2 * DIM + h * DH + c2 * 2];
        *(float2*)&sv[r][c2 * 2] = v;
    }
    __syncthreads();
    for (int e = t; e < CTI * (DH / 2); e += 256) {
        int r = e >> 5, c2 = e & 31;
        float2 acc = make_float2(0.f, 0.f);
        #pragma unroll
        for (int k = 0; k < KW; k++) {
            float2 v = *(float2*)&sv[r + k][c2 * 2];
            acc.x += w[k] * v.x; acc.y += w[k] * v.y;
        }
        *(float2*)&g_osort[(long)(i0 + r) * DIM + h * DH + c2 * 2] = acc;
    }
}

// ---- flash core: O[64rows x 64] = softmax_online(Aq @ Kt^T) @ V over chunks ----
// AQROW/KROW/VROW: fp32 row pointers with given strides. Writes/accumulates per OSTORE.
// flash3: a3v = softmax(ql @ k^T) @ v, online over N_TOK (STORE to a3v)
__global__ void __launch_bounds__(128) flash3_kernel() {
    __shared__ unsigned Ks[64][36];
    __shared__ unsigned Ws[64][36];
    int h = blockIdx.y, bm = blockIdx.x * 64;   // landmark rows
    int tid = threadIdx.x, lane = tid & 31, wid = tid >> 5;
    int g = lane >> 2, tg = lane & 3, wr0 = wid * 16;

    // stage ql tile [64 x 64]
    for (int e = tid; e < 64 * 8; e += 128) {
        int r = e >> 3, d8 = (e & 7) * 8;
        const float* q = &g_ql[((long)h * NC + bm + r) * DH + d8];
        float4 v0 = *(const float4*)q, v1 = *(const float4*)(q + 4);
        int c2 = d8 >> 1;
        Ks[r][c2]     = f2h2(v0.x, v0.y);
        Ks[r][c2 + 1] = f2h2(v0.z, v0.w);
        Ks[r][c2 + 2] = f2h2(v1.x, v1.y);
        Ks[r][c2 + 3] = f2h2(v1.z, v1.w);
    }
    __syncthreads();
    unsigned qf[4][4];
    #pragma unroll
    for (int c = 0; c < 4; c++) {
        qf[c][0] = Ks[wr0 + g    ][c * 8 + tg];
        qf[c][1] = Ks[wr0 + g + 8][c * 8 + tg];
        qf[c][2] = Ks[wr0 + g    ][c * 8 + tg + 4];
        qf[c][3] = Ks[wr0 + g + 8][c * 8 + tg + 4];
    }

    float m0 = -1e30f, m1 = -1e30f, l0 = 0.f, l1 = 0.f;
    float O[8][4] = {};
    const float* kb = g_qkv + DIM + h * DH;       // k rows, stride QKVW
    const float* vb = g_qkv + 2 * DIM + h * DH;   // v rows, stride QKVW

    for (int jc = 0; jc < N_TOK; jc += 64) {
        __syncthreads();
        for (int e = tid; e < 64 * 8; e += 128) {
            int n = e >> 3, d8 = (e & 7) * 8;
            const float* kp = kb + (long)(jc + n) * QKVW + d8;
            float4 v0 = *(const float4*)kp, v1 = *(const float4*)(kp + 4);
            int c2 = d8 >> 1;
            Ks[n][c2]     = f2h2(v0.x, v0.y);
            Ks[n][c2 + 1] = f2h2(v0.z, v0.w);
            Ks[n][c2 + 2] = f2h2(v1.x, v1.y);
            Ks[n][c2 + 3] = f2h2(v1.z, v1.w);
        }
        for (int e = tid; e < 32 * 16; e += 128) {
            int j2 = e >> 4, d4 = (e & 15) * 4;
            const float* w0 = vb + (long)(jc + 2 * j2) * QKVW + d4;
            const float* w1 = w0 + QKVW;
            float4 a = *(const float4*)w0, b = *(const float4*)w1;
            Ws[d4 + 0][j2] = f2h2(a.x, b.x);
            Ws[d4 + 1][j2] = f2h2(a.y, b.y);
            Ws[d4 + 2][j2] = f2h2(a.z, b.z);
            Ws[d4 + 3][j2] = f2h2(a.w, b.w);
        }
        __syncthreads();

        float s[8][4] = {};
        #pragma unroll
        for (int c = 0; c < 4; c++) {
            #pragma unroll
            for (int nt = 0; nt < 8; nt++) {
                unsigned bf[2];
                bf[0] = Ks[nt * 8 + g][c * 8 + tg];
                bf[1] = Ks[nt * 8 + g][c * 8 + tg + 4];
                mma_f16(s[nt], qf[c], bf);
            }
        }

        float mc0 = -1e30f, mc1 = -1e30f;
        #pragma unroll
        for (int nt = 0; nt < 8; nt++) {
            mc0 = fmaxf(mc0, fmaxf(s[nt][0], s[nt][1]));
            mc1 = fmaxf(mc1, fmaxf(s[nt][2], s[nt][3]));
        }
        mc0 = fmaxf(mc0, __shfl_xor_sync(~0u, mc0, 1));
        mc0 = fmaxf(mc0, __shfl_xor_sync(~0u, mc0, 2));
        mc1 = fmaxf(mc1, __shfl_xor_sync(~0u, mc1, 1));
        mc1 = fmaxf(mc1, __shfl_xor_sync(~0u, mc1, 2));
        float mn0 = fmaxf(m0, mc0), mn1 = fmaxf(m1, mc1);
        float sc0 = __expf(m0 - mn0), sc1 = __expf(m1 - mn1);
        float ps0 = 0.f, ps1 = 0.f;
        float p[8][4];
        #pragma unroll
        for (int nt = 0; nt < 8; nt++) {
            p[nt][0] = __expf(s[nt][0] - mn0);
            p[nt][1] = __expf(s[nt][1] - mn0);
            p[nt][2] = __expf(s[nt][2] - mn1);
            p[nt][3] = __expf(s[nt][3] - mn1);
            ps0 += p[nt][0] + p[nt][1];
            ps1 += p[nt][2] + p[nt][3];
            O[nt][0] *= sc0; O[nt][1] *= sc0; O[nt][2] *= sc1; O[nt][3] *= sc1;
        }
        ps0 += __shfl_xor_sync(~0u, ps0, 1); ps0 += __shfl_xor_sync(~0u, ps0, 2);
        ps1 += __shfl_xor_sync(~0u, ps1, 1); ps1 += __shfl_xor_sync(~0u, ps1, 2);
        l0 = l0 * sc0 + ps0; l1 = l1 * sc1 + ps1;
        m0 = mn0; m1 = mn1;

        unsigned pf[4][4];
        #pragma unroll
        for (int c = 0; c < 4; c++) {
            pf[c][0] = f2h2(p[2*c][0],   p[2*c][1]);
            pf[c][1] = f2h2(p[2*c][2],   p[2*c][3]);
            pf[c][2] = f2h2(p[2*c+1][0], p[2*c+1][1]);
            pf[c][3] = f2h2(p[2*c+1][2], p[2*c+1][3]);
        }
        #pragma unroll
        for (int c = 0; c < 4; c++) {
            #pragma unroll
            for (int nt = 0; nt < 8; nt++) {
                unsigned bf[2];
                bf[0] = Ws[nt * 8 + g][c * 8 + tg];
                bf[1] = Ws[nt * 8 + g][c * 8 + tg + 4];
                mma_f16(O[nt], pf[c], bf);
            }
        }
    }

    float inv0 = 1.f / l0, inv1 = 1.f / l1;
    long r0 = (long)h * NC + bm + wr0 + g, r1 = r0 + 8;
    #pragma unroll
    for (int nt = 0; nt < 8; nt++) {
        int col = nt * 8 + 2 * tg;
        *(float2*)&g_a3v[r0 * DH + col] = make_float2(O[nt][0] * inv0, O[nt][1] * inv0);
        *(float2*)&g_a3v[r1 * DH + col] = make_float2(O[nt][2] * inv1, O[nt][3] * inv1);
    }
}

// flash1: osort += softmax(q @ kl^T) @ wm (accumulate over conv base)
__global__ void __launch_bounds__(128) flash1_kernel() {
    __shared__ unsigned Ks[64][36];
    __shared__ unsigned Ws[64][36];
    int h = blockIdx.y, bm = blockIdx.x * 64;
    int tid = threadIdx.x, lane = tid & 31, wid = tid >> 5;
    int g = lane >> 2, tg = lane & 3, wr0 = wid * 16;

    for (int e = tid; e < 64 * 8; e += 128) {
        int r = e >> 3, d8 = (e & 7) * 8;
        const float* q = &g_qkv[(long)(bm + r) * QKVW + h * DH + d8];
        float4 v0 = *(const float4*)q, v1 = *(const float4*)(q + 4);
        int c2 = d8 >> 1;
        Ks[r][c2]     = f2h2(v0.x, v0.y);
        Ks[r][c2 + 1] = f2h2(v0.z, v0.w);
        Ks[r][c2 + 2] = f2h2(v1.x, v1.y);
        Ks[r][c2 + 3] = f2h2(v1.z, v1.w);
    }
    __syncthreads();
    unsigned qf[4][4];
    #pragma unroll
    for (int c = 0; c < 4; c++) {
        qf[c][0] = Ks[wr0 + g    ][c * 8 + tg];
        qf[c][1] = Ks[wr0 + g + 8][c * 8 + tg];
        qf[c][2] = Ks[wr0 + g    ][c * 8 + tg + 4];
        qf[c][3] = Ks[wr0 + g + 8][c * 8 + tg + 4];
    }

    float m0 = -1e30f, m1 = -1e30f, l0 = 0.f, l1 = 0.f;
    float O[8][4] = {};
    const float* klb = g_kl + (long)h * NC * DH;
    const float* wmb = g_wm + (long)h * NC * DH;

    for (int jc = 0; jc < NC; jc += 64) {
        __syncthreads();
        for (int e = tid; e < 64 * 8; e += 128) {
            int n = e >> 3, d8 = (e & 7) * 8;
            const float* kp = &klb[(long)(jc + n) * DH + d8];
            float4 v0 = *(const float4*)kp, v1 = *(const float4*)(kp + 4);
            int c2 = d8 >> 1;
            Ks[n][c2]     = f2h2(v0.x, v0.y);
            Ks[n][c2 + 1] = f2h2(v0.z, v0.w);
            Ks[n][c2 + 2] = f2h2(v1.x, v1.y);
            Ks[n][c2 + 3] = f2h2(v1.z, v1.w);
        }
        for (int e = tid; e < 32 * 16; e += 128) {
            int j2 = e >> 4, d4 = (e & 15) * 4;
            const float* w0 = &wmb[(long)(jc + 2 * j2) * DH + d4];
            const float* w1 = w0 + DH;
            float4 a = *(const float4*)w0, b = *(const float4*)w1;
            Ws[d4 + 0][j2] = f2h2(a.x, b.x);
            Ws[d4 + 1][j2] = f2h2(a.y, b.y);
            Ws[d4 + 2][j2] = f2h2(a.z, b.z);
            Ws[d4 + 3][j2] = f2h2(a.w, b.w);
        }
        __syncthreads();

        float s[8][4] = {};
        #pragma unroll
        for (int c = 0; c < 4; c++) {
            #pragma unroll
            for (int nt = 0; nt < 8; nt++) {
                unsigned bf[2];
                bf[0] = Ks[nt * 8 + g][c * 8 + tg];
                bf[1] = Ks[nt * 8 + g][c * 8 + tg + 4];
                mma_f16(s[nt], qf[c], bf);
            }
        }

        float mc0 = -1e30f, mc1 = -1e30f;
        #pragma unroll
        for (int nt = 0; nt < 8; nt++) {
            mc0 = fmaxf(mc0, fmaxf(s[nt][0], s[nt][1]));
            mc1 = fmaxf(mc1, fmaxf(s[nt][2], s[nt][3]));
        }
        mc0 = fmaxf(mc0, __shfl_xor_sync(~0u, mc0, 1));
        mc0 = fmaxf(mc0, __shfl_xor_sync(~0u, mc0, 2));
        mc1 = fmaxf(mc1, __shfl_xor_sync(~0u, mc1, 1));
        mc1 = fmaxf(mc1, __shfl_xor_sync(~0u, mc1, 2));
        float mn0 = fmaxf(m0, mc0), mn1 = fmaxf(m1, mc1);
        float sc0 = __expf(m0 - mn0), sc1 = __expf(m1 - mn1);
        float ps0 = 0.f, ps1 = 0.f;
        float p[8][4];
        #pragma unroll
        for (int nt = 0; nt < 8; nt++) {
            p[nt][0] = __expf(s[nt][0] - mn0);
            p[nt][1] = __expf(s[nt][1] - mn0);
            p[nt][2] = __expf(s[nt][2] - mn1);
            p[nt][3] = __expf(s[nt][3] - mn1);
            ps0 += p[nt][0] + p[nt][1];
            ps1 += p[nt][2] + p[nt][3];
            O[nt][0] *= sc0; O[nt][1] *= sc0; O[nt][2] *= sc1; O[nt][3] *= sc1;
        }
        ps0 += __shfl_xor_sync(~0u, ps0, 1); ps0 += __shfl_xor_sync(~0u, ps0, 2);
        ps1 += __shfl_xor_sync(~0u, ps1, 1); ps1 += __shfl_xor_sync(~0u, ps1, 2);
        l0 = l0 * sc0 + ps0; l1 = l1 * sc1 + ps1;
        m0 = mn0; m1 = mn1;

        unsigned pf[4][4];
        #pragma unroll
        for (int c = 0; c < 4; c++) {
            pf[c][0] = f2h2(p[2*c][0],   p[2*c][1]);
            pf[c][1] = f2h2(p[2*c][2],   p[2*c][3]);
            pf[c][2] = f2h2(p[2*c+1][0], p[2*c+1][1]);
            pf[c][3] = f2h2(p[2*c+1][2], p[2*c+1][3]);
        }
        #pragma unroll
        for (int c = 0; c < 4; c++) {
            #pragma unroll
            for (int nt = 0; nt < 8; nt++) {
                unsigned bf[2];
                bf[0] = Ws[nt * 8 + g][c * 8 + tg];
                bf[1] = Ws[nt * 8 + g][c * 8 + tg + 4];
                mma_f16(O[nt], pf[c], bf);
            }
        }
    }

    float inv0 = 1.f / l0, inv1 = 1.f / l1;
    int r0 = bm + wr0 + g, r1 = r0 + 8;
    #pragma unroll
    for (int nt = 0; nt < 8; nt++) {
        int col = h * DH + nt * 8 + 2 * tg;
        float2* o0 = (float2*)&g_osort[(long)r0 * DIM + col];
        float2* o1 = (float2*)&g_osort[(long)r1 * DIM + col];
        float2 c0 = *o0, c1 = *o1;
        *o0 = make_float2(c0.x + O[nt][0] * inv0, c0.y + O[nt][1] * inv0);
        *o1 = make_float2(c1.x + O[nt][2] * inv1, c1.y + O[nt][3] * inv1);
    }
}

// ---------------- small GEMM (wm = z @ a3v): half A, fp32 B/C, tf32 MMA ----------------
__global__ void __launch_bounds__(128) small_gemm_kernel(
    const __half* __restrict__ A, int lda, long sA,
    const float* __restrict__ B, int ldb, long sB,
    float* __restrict__ C, int ldc, long sC, int K)
{
    __shared__ unsigned As[2][64][20];
    __shared__ unsigned Bs[2][16][72];
    int z = blockIdx.z;
    A += (long)z * sA; B += (long)z * sB; C += (long)z * sC;
    int bm = blockIdx.y * 64, bn = blockIdx.x * 64;
    int tid = threadIdx.x, lane = tid & 31, wid = tid >> 5;
    int warpM = wid >> 1, warpN = wid & 1, g = lane >> 2, tg = lane & 3;
    int ar = tid >> 1, ak = (tid & 1) * 8;
    const __half* Ap = A + (long)(bm + ar) * lda + ak;
    int bk = tid >> 4, bnn = (tid & 15) * 4;
    const float* Bp = B + (long)bk * ldb + bn + bnn;
    float aR[8], bR[8];
    float acc[2][4][4] = {};

    #define SLDG(k0) do {                                                      \
        uint4 _av = __ldcg((const uint4*)(Ap + (k0)));                         \
        const __half* _ah = (const __half*)&_av;                               \
        _Pragma("unroll")                                                      \
        for (int _i = 0; _i < 8; _i++) aR[_i] = __half2float(_ah[_i]);         \
        float4 _b0 = *(const float4*)(Bp + (long)(k0) * ldb);                  \
        float4 _b1 = *(const float4*)(Bp + (long)((k0) + 8) * ldb);            \
        bR[0]=_b0.x; bR[1]=_b0.y; bR[2]=_b0.z; bR[3]=_b0.w;                    \
        bR[4]=_b1.x; bR[5]=_b1.y; bR[6]=_b1.z; bR[7]=_b1.w;                    \
    } while (0)
    #define SST(p) do {                                                        \
        _Pragma("unroll")                                                      \
        for (int _i = 0; _i < 8; _i++) As[p][ar][ak + _i] = f2tf32(aR[_i]);    \
        _Pragma("unroll")                                                      \
        for (int _i = 0; _i < 4; _i++) {                                       \
            Bs[p][bk][bnn + _i] = f2tf32(bR[_i]);                              \
            Bs[p][bk + 8][bnn + _i] = f2tf32(bR[4 + _i]);                      \
        }                                                                      \
    } while (0)

    SLDG(0); SST(0);
    __syncthreads();
    int buf = 0;
    for (int k0 = 0; k0 < K; k0 += 16) {
        bool nxt = (k0 + 16) < K;
        if (nxt) SLDG(k0 + 16);
        #pragma unroll
        for (int kk = 0; kk < 16; kk += 8) {
            unsigned af[2][4];
            #pragma unroll
            for (int mt = 0; mt < 2; mt++) {
                int r0 = warpM * 32 + mt * 16;
                af[mt][0] = As[buf][r0 + g    ][kk + tg];
                af[mt][1] = As[buf][r0 + g + 8][kk + tg];
                af[mt][2] = As[buf][r0 + g    ][kk + tg + 4];
                af[mt][3] = As[buf][r0 + g + 8][kk + tg + 4];
            }
            unsigned bf[4][2];
            #pragma unroll
            for (int nt = 0; nt < 4; nt++) {
                int c0 = warpN * 32 + nt * 8;
                bf[nt][0] = Bs[buf][kk + tg    ][c0 + g];
                bf[nt][1] = Bs[buf][kk + tg + 4][c0 + g];
            }
            #pragma unroll
            for (int mt = 0; mt < 2; mt++)
                #pragma unroll
                for (int nt = 0; nt < 4; nt++)
                    mma_tf32(acc[mt][nt], af[mt], bf[nt]);
        }
        if (nxt) { SST(buf ^ 1); __syncthreads(); }
        buf ^= 1;
    }
    #pragma unroll
    for (int mt = 0; mt < 2; mt++) {
        int r0 = bm + warpM * 32 + mt * 16 + g, r1 = r0 + 8;
        #pragma unroll
        for (int nt = 0; nt < 4; nt++) {
            int col = bn + warpN * 32 + nt * 8 + 2 * tg;
            *(float2*)&C[(long)r0 * ldc + col] = make_float2(acc[mt][nt][0], acc[mt][nt][1]);
            *(float2*)&C[(long)r1 * ldc + col] = make_float2(acc[mt][nt][2], acc[mt][nt][3]);
        }
    }
    #undef SLDG
    #undef SST
}

// ---------------- BM=128 tf32 GEMM (a2 only) ----------------
__global__ void __launch_bounds__(256) a2_gemm_kernel(
    const float* __restrict__ A, const float* __restrict__ B, float* __restrict__ C)
{
    __shared__ unsigned As[2][128][20];
    __shared__ unsigned Bs[2][16][136];
    long SL = (long)NC * DH, S2 = (long)NC * NC;
    int batch = blockIdx.z;
    A += batch * SL; B += batch * SL; C += batch * S2;
    int bm = blockIdx.y * 128, bn = blockIdx.x * 128;
    int tid = threadIdx.x, lane = tid & 31, wid = tid >> 5;
    int warpM = wid >> 1, warpN = wid & 1, g = lane >> 2, tg = lane & 3;
    int ar = tid >> 1, ak = (tid & 1) * 8;
    const float* Ap = A + (long)(bm + ar) * DH + ak;
    int bnn = tid >> 1, bk = (tid & 1) * 8;
    const float* Bp = B + (long)(bn + bnn) * DH + bk;
    float aR[8], bR[8];
    float acc[2][8][4];
    #pragma unroll
    for (int i = 0; i < 2; i++)
        #pragma unroll
        for (int j = 0; j < 8; j++)
            #pragma unroll
            for (int l = 0; l < 4; l++) acc[i][j][l] = 0.f;

    #define ALDG(k0) do {                                                      \
        float4 _a0 = *(const float4*)(Ap + (k0));                              \
        float4 _a1 = *(const float4*)(Ap + (k0) + 4);                          \
        aR[0]=_a0.x; aR[1]=_a0.y; aR[2]=_a0.z; aR[3]=_a0.w;                    \
        aR[4]=_a1.x; aR[5]=_a1.y; aR[6]=_a1.z; aR[7]=_a1.w;                    \
        float4 _b0 = *(const float4*)(Bp + (k0));                              \
        float4 _b1 = *(const float4*)(Bp + (k0) + 4);                          \
        bR[0]=_b0.x; bR[1]=_b0.y; bR[2]=_b0.z; bR[3]=_b0.w;                    \
        bR[4]=_b1.x; bR[5]=_b1.y; bR[6]=_b1.z; bR[7]=_b1.w;                    \
    } while (0)
    #define AST(p) do {                                                        \
        _Pragma("unroll")                                                      \
        for (int _i = 0; _i < 8; _i++) As[p][ar][ak + _i] = f2tf32(aR[_i]);    \
        _Pragma("unroll")                                                      \
        for (int _i = 0; _i < 8; _i++) Bs[p][bk + _i][bnn] = f2tf32(bR[_i]);   \
    } while (0)

    ALDG(0); AST(0);
    __syncthreads();
    int buf = 0;
    for (int k0 = 0; k0 < DH; k0 += 16) {
        bool nxt = (k0 + 16) < DH;
        if (nxt) ALDG(k0 + 16);
        #pragma unroll
        for (int kk = 0; kk < 16; kk += 8) {
            unsigned af[2][4];
            #pragma unroll
            for (int mt = 0; mt < 2; mt++) {
                int r0 = warpM * 32 + mt * 16;
                af[mt][0] = As[buf][r0 + g    ][kk + tg];
                af[mt][1] = As[buf][r0 + g + 8][kk + tg];
                af[mt][2] = As[buf][r0 + g    ][kk + tg + 4];
                af[mt][3] = As[buf][r0 + g + 8][kk + tg + 4];
            }
            unsigned bf[8][2];
            #pragma unroll
            for (int nt = 0; nt < 8; nt++) {
                int c0 = warpN * 64 + nt * 8;
                bf[nt][0] = Bs[buf][kk + tg    ][c0 + g];
                bf[nt][1] = Bs[buf][kk + tg + 4][c0 + g];
            }
            #pragma unroll
            for (int mt = 0; mt < 2; mt++)
                #pragma unroll
                for (int nt = 0; nt < 8; nt++)
                    mma_tf32(acc[mt][nt], af[mt], bf[nt]);
        }
        if (nxt) { AST(buf ^ 1); __syncthreads(); }
        buf ^= 1;
    }
    #pragma unroll
    for (int mt = 0; mt < 2; mt++) {
        int r0 = bm + warpM * 32 + mt * 16 + g, r1 = r0 + 8;
        #pragma unroll
        for (int nt = 0; nt < 8; nt++) {
            int col = bn + warpN * 64 + nt * 8 + 2 * tg;
            *(float2*)&C[(long)r0 * NC + col] = make_float2(acc[mt][nt][0], acc[mt][nt][1]);
            *(float2*)&C[(long)r1 * NC + col] = make_float2(acc[mt][nt][2], acc[mt][nt][3]);
        }
    }
    #undef ALDG
    #undef AST
}

extern "C" void kernel_launch(void* const* d_in, const int* in_sizes, int n_in,
                              void* d_out, int out_size)
{
    const float* x      = (const float*)d_in[0];
    const int*   labels = (const int*)  d_in[1];
    const float* w_qkv  = (const float*)d_in[2];
    const float* w_res  = (const float*)d_in[3];
    const float* w_out  = (const float*)d_in[4];
    const float* b_out  = (const float*)d_in[5];
    float* out = (float*)d_out;

    float *qkv, *a2, *ql, *kl, *a3v, *wm, *osort;
    __half *a2h, *xz, *u1, *u2, *za, *zb;
    int* idx;
    cudaGetSymbolAddress((void**)&qkv,  g_qkv);
    cudaGetSymbolAddress((void**)&a2,   g_a2);
    cudaGetSymbolAddress((void**)&a2h,  g_a2h);
    cudaGetSymbolAddress((void**)&xz,   g_xz);
    cudaGetSymbolAddress((void**)&u1,   g_u1);
    cudaGetSymbolAddress((void**)&u2,   g_u2);
    cudaGetSymbolAddress((void**)&za,   g_za);
    cudaGetSymbolAddress((void**)&zb,   g_zb);
    cudaGetSymbolAddress((void**)&ql,   g_ql);
    cudaGetSymbolAddress((void**)&kl,   g_kl);
    cudaGetSymbolAddress((void**)&a3v,  g_a3v);
    cudaGetSymbolAddress((void**)&wm,   g_wm);
    cudaGetSymbolAddress((void**)&osort,g_osort);
    cudaGetSymbolAddress((void**)&idx,  g_idx);

    static cudaStream_t s2 = nullptr;
    static cudaEvent_t evS = nullptr, evL = nullptr, evJ = nullptr;
    if (!s2) {
        cudaStreamCreateWithFlags(&s2, cudaStreamNonBlocking);
        cudaEventCreateWithFlags(&evS, cudaEventDisableTiming);
        cudaEventCreateWithFlags(&evL, cudaEventDisableTiming);
        cudaEventCreateWithFlags(&evJ, cudaEventDisableTiming);
    }

    const long S2 = (long)NC * NC;
    const long SL = (long)NC * DH;

    // sort
    init_scalars_kernel<<<1, 1>>>();
    hist_kernel <<<64, 256>>>(labels);
    scan_kernel <<<1, 512>>>();
    place_kernel<<<64, 256>>>(labels);
    cudaEventRecord(evS, 0);

    // qk = x[idx] @ w_qkv[0:1024]^T (serial); v on s2
    tt_gemm<true, false><<<dim3(1024 / 128, N_TOK / 128, 1), 256>>>(
        x, DIM, 0, w_qkv, DIM, 0, qkv, QKVW, 0, DIM, 1.f, idx, nullptr, nullptr);

    landmark_kernel<<<dim3(NC, NH), 128>>>();
    cudaEventRecord(evL, 0);

    // --- s2 branch: v GEMM -> flash3 (a3v) -> conv ---
    cudaStreamWaitEvent(s2, evS, 0);
    tt_gemm<true, false><<<dim3(512 / 128, N_TOK / 128, 1), 256, 0, s2>>>(
        x, DIM, 0, w_qkv + (long)1024 * DIM, DIM, 0, qkv + 1024, QKVW, 0,
        DIM, 1.f, idx, nullptr, nullptr);
    cudaStreamWaitEvent(s2, evL, 0);
    flash3_kernel<<<dim3(NC / 64, NH), 128, 0, s2>>>();
    conv_add_kernel<<<dim3(N_TOK / CTI, NH), 256, 0, s2>>>(w_res);
    cudaEventRecord(evJ, s2);

    // --- main branch: a2 + fused pinv ---
    a2_gemm_kernel<<<dim3(NC / 128, NC / 128, NH), 256>>>(ql, kl, a2);
    softmax_kernel<<<NH * NC, 256>>>(a2, NC);
    colsum_kernel<<<NH, 512>>>();
    zinit_kernel<<<(NH * NC * NC) / 256, 256>>>();

    pinv_fused_kernel<<<128, 256>>>(a2h, xz, u1, u2, za, zb);

    // join: wm needs a3v (s2); flash1 needs conv-written osort (s2)
    cudaStreamWaitEvent(0, evJ, 0);
    small_gemm_kernel<<<dim3(1, NC / 64, NH), 128>>>(za, NC, S2, a3v, DH, SL, wm, DH, SL, NC);

    flash1_kernel<<<dim3(N_TOK / 64, NH), 128>>>();

    // output projection + bias + scatter
    tt_gemm<true, true><<<dim3(DIM / 128, N_TOK / 128, 1), 256>>>(
        osort, DIM, 0, w_out, DIM, 0, out, DIM, 0, DIM, 1.f, nullptr, idx, b_out);
}

// round 16
// speedup vs baseline: 1.7318x; 1.7318x over previous
#include <cuda_runtime.h>
#include <cuda_fp16.h>
#include <math.h>

#define N_TOK 16384
#define DIM   512
#define NH    8
#define DH    64
#define NC    512
#define QKVW  1536
#define KW    33

__device__ float  g_qkv [(long)N_TOK*QKVW];
__device__ __half g_sim3[(long)NH*NC*N_TOK];
__device__ float  g_a2  [NH*NC*NC];
__device__ __half g_a2h [NH*NC*NC];
__device__ __half g_xz  [NH*NC*NC];
__device__ __half g_u1  [NH*NC*NC];
__device__ __half g_u2  [NH*NC*NC];
__device__ __half g_za  [NH*NC*NC];
__device__ __half g_zb  [NH*NC*NC];
__device__ float  g_ql  [NH*NC*DH];
__device__ float  g_kl  [NH*NC*DH];
__device__ float  g_a3v [NH*NC*DH];
__device__ float  g_wm  [NH*NC*DH];
__device__ float  g_osort[(long)N_TOK*DIM];
__device__ float2 g_st3[NH*NC];
__device__ int    g_idx [N_TOK];
__device__ int    g_counts [NC];
__device__ int    g_offsets[NC];
__device__ int    g_bh[64*NC];
__device__ unsigned g_maxcs;
__device__ unsigned g_bar;

__device__ __forceinline__ unsigned f2tf32(float v) {
    unsigned r; asm("cvt.rna.tf32.f32 %0, %1;" : "=r"(r) : "f"(v)); return r;
}
__device__ __forceinline__ void mma_tf32(float* c, const unsigned* a, const unsigned* b) {
    asm volatile("mma.sync.aligned.m16n8k8.row.col.f32.tf32.tf32.f32 "
        "{%0,%1,%2,%3}, {%4,%5,%6,%7}, {%8,%9}, {%0,%1,%2,%3};"
        : "+f"(c[0]), "+f"(c[1]), "+f"(c[2]), "+f"(c[3])
        : "r"(a[0]), "r"(a[1]), "r"(a[2]), "r"(a[3]), "r"(b[0]), "r"(b[1]));
}
__device__ __forceinline__ unsigned f2h2(float a, float b) {
    __half2 h = __floats2half2_rn(a, b);
    return *(unsigned*)&h;
}
__device__ __forceinline__ void mma_f16(float* c, const unsigned* a, const unsigned* b) {
    asm volatile("mma.sync.aligned.m16n8k16.row.col.f32.f16.f16.f32 "
        "{%0,%1,%2,%3}, {%4,%5,%6,%7}, {%8,%9}, {%0,%1,%2,%3};"
        : "+f"(c[0]), "+f"(c[1]), "+f"(c[2]), "+f"(c[3])
        : "r"(a[0]), "r"(a[1]), "r"(a[2]), "r"(a[3]), "r"(b[0]), "r"(b[1]));
}

// ============ tt_gemm (fp32 in, fp16 MMA): 128x128 tile, 256 thr, K-chunk 32 ============
// OUTH: C is __half (pass sC in float-elems = half-elems/2; ldc in half elems)
template<bool TB, bool SCAT, bool OUTH>
__global__ void __launch_bounds__(256) tt_gemm(
    const float* __restrict__ A, int lda, long sA,
    const float* __restrict__ B, int ldb, long sB,
    float* __restrict__ C, int ldc, long sC,
    int K, float alpha,
    const int* __restrict__ gatherA, const int* __restrict__ scatterC,
    const float* __restrict__ bias)
{
    __shared__ unsigned As[2][128][20];
    __shared__ unsigned Bs[2][16][132];
    int h = blockIdx.z;
    A += (long)h * sA; B += (long)h * sB; C += (long)h * sC;
    int bm = blockIdx.y * 128, bn = blockIdx.x * 128;
    int tid = threadIdx.x, lane = tid & 31, wid = tid >> 5;
    int warpM = wid >> 1, warpN = wid & 1, g = lane >> 2, tg = lane & 3;

    int ar = tid >> 1, akb = (tid & 1) * 16;
    int grow = bm + ar;
    if (gatherA) grow = gatherA[grow];
    const float* Ap = A + (long)grow * lda + akb;

    const float* Bp;
    int bsn = 0, bsk = 0, bp2 = 0;
    if (TB) { bsn = tid >> 1; bsk = (tid & 1) * 16;
              Bp = B + (long)(bn + bsn) * ldb + bsk; }
    else    { bp2 = tid >> 4; bsn = (tid & 15) * 8;
              Bp = B + (long)(2 * bp2) * ldb + bn + bsn; }

    float aR[16], bR[16];
    float acc[2][8][4];
    #pragma unroll
    for (int i = 0; i < 2; i++)
        #pragma unroll
        for (int j = 0; j < 8; j++)
            #pragma unroll
            for (int l = 0; l < 4; l++) acc[i][j][l] = 0.f;

    #define TLDG(k0) do {                                                      \
        float4 _a0 = *(const float4*)(Ap + (k0));                              \
        float4 _a1 = *(const float4*)(Ap + (k0) + 4);                          \
        float4 _a2 = *(const float4*)(Ap + (k0) + 8);                          \
        float4 _a3 = *(const float4*)(Ap + (k0) + 12);                         \
        aR[0]=_a0.x; aR[1]=_a0.y; aR[2]=_a0.z; aR[3]=_a0.w;                    \
        aR[4]=_a1.x; aR[5]=_a1.y; aR[6]=_a1.z; aR[7]=_a1.w;                    \
        aR[8]=_a2.x; aR[9]=_a2.y; aR[10]=_a2.z; aR[11]=_a2.w;                  \
        aR[12]=_a3.x; aR[13]=_a3.y; aR[14]=_a3.z; aR[15]=_a3.w;                \
        if (TB) {                                                              \
            float4 _b0 = *(const float4*)(Bp + (k0));                          \
            float4 _b1 = *(const float4*)(Bp + (k0) + 4);                      \
            float4 _b2 = *(const float4*)(Bp + (k0) + 8);                      \
            float4 _b3 = *(const float4*)(Bp + (k0) + 12);                     \
            bR[0]=_b0.x; bR[1]=_b0.y; bR[2]=_b0.z; bR[3]=_b0.w;                \
            bR[4]=_b1.x; bR[5]=_b1.y; bR[6]=_b1.z; bR[7]=_b1.w;                \
            bR[8]=_b2.x; bR[9]=_b2.y; bR[10]=_b2.z; bR[11]=_b2.w;              \
            bR[12]=_b3.x; bR[13]=_b3.y; bR[14]=_b3.z; bR[15]=_b3.w;            \
        } else {                                                               \
            const float* _r0 = Bp + (long)(k0) * ldb;                          \
            const float* _r1 = _r0 + ldb;                                      \
            float4 _x0 = *(const float4*)(_r0);                                \
            float4 _x1 = *(const float4*)(_r0 + 4);                            \
            float4 _y0 = *(const float4*)(_r1);                                \
            float4 _y1 = *(const float4*)(_r1 + 4);                            \
            bR[0]=_x0.x; bR[1]=_x0.y; bR[2]=_x0.z; bR[3]=_x0.w;                \
            bR[4]=_x1.x; bR[5]=_x1.y; bR[6]=_x1.z; bR[7]=_x1.w;                \
            bR[8]=_y0.x; bR[9]=_y0.y; bR[10]=_y0.z; bR[11]=_y0.w;              \
            bR[12]=_y1.x; bR[13]=_y1.y; bR[14]=_y1.z; bR[15]=_y1.w;            \
        }                                                                      \
    } while (0)

    #define TST(p) do {                                                        \
        int _cb = (tid & 1) * 8;                                               \
        _Pragma("unroll")                                                      \
        for (int _j = 0; _j < 4; _j++)                                         \
            *(uint2*)&As[p][ar][_cb + 2 * _j] = make_uint2(                    \
                f2h2(aR[2*_j], aR[2*_j+1]), f2h2(aR[2*_j+8], aR[2*_j+9]));     \
        if (TB) {                                                              \
            int _kb2 = (tid & 1) * 8, _s = (bsn & 7) * 16 + (bsn >> 3);        \
            _Pragma("unroll")                                                  \
            for (int _j = 0; _j < 8; _j++)                                     \
                Bs[p][_kb2 + _j][_s] = f2h2(bR[2*_j], bR[2*_j+1]);             \
        } else {                                                               \
            int _t = tid & 15;                                                 \
            _Pragma("unroll")                                                  \
            for (int _j = 0; _j < 8; _j++)                                     \
                Bs[p][bp2][_j * 16 + _t] = f2h2(bR[_j], bR[8 + _j]);           \
        }                                                                      \
    } while (0)

    TLDG(0); TST(0);
    __syncthreads();
    int buf = 0;
    for (int k0 = 0; k0 < K; k0 += 32) {
        bool nxt = (k0 + 32) < K;
        if (nxt) TLDG(k0 + 32);
        #pragma unroll
        for (int c = 0; c < 2; c++) {
            unsigned af[2][4];
            #pragma unroll
            for (int mt = 0; mt < 2; mt++) {
                int r0 = warpM * 32 + mt * 16;
                uint2 p0 = *(const uint2*)&As[buf][r0 + g    ][c * 8 + 2 * tg];
                uint2 p1 = *(const uint2*)&As[buf][r0 + g + 8][c * 8 + 2 * tg];
                af[mt][0] = p0.x; af[mt][1] = p1.x; af[mt][2] = p0.y; af[mt][3] = p1.y;
            }
            unsigned bf[8][2];
            {
                int s0 = g * 16 + warpN * 8;
                uint4 q0 = *(const uint4*)&Bs[buf][c * 8 + tg    ][s0];
                uint4 q1 = *(const uint4*)&Bs[buf][c * 8 + tg    ][s0 + 4];
                uint4 q2 = *(const uint4*)&Bs[buf][c * 8 + tg + 4][s0];
                uint4 q3 = *(const uint4*)&Bs[buf][c * 8 + tg + 4][s0 + 4];
                bf[0][0]=q0.x; bf[1][0]=q0.y; bf[2][0]=q0.z; bf[3][0]=q0.w;
                bf[4][0]=q1.x; bf[5][0]=q1.y; bf[6][0]=q1.z; bf[7][0]=q1.w;
                bf[0][1]=q2.x; bf[1][1]=q2.y; bf[2][1]=q2.z; bf[3][1]=q2.w;
                bf[4][1]=q3.x; bf[5][1]=q3.y; bf[6][1]=q3.z; bf[7][1]=q3.w;
            }
            #pragma unroll
            for (int mt = 0; mt < 2; mt++)
                #pragma unroll
                for (int nt = 0; nt < 8; nt++)
                    mma_f16(acc[mt][nt], af[mt], bf[nt]);
        }
        if (nxt) { TST(buf ^ 1); __syncthreads(); }
        buf ^= 1;
    }

    #pragma unroll
    for (int mt = 0; mt < 2; mt++) {
        int r0 = bm + warpM * 32 + mt * 16 + g, r1 = r0 + 8;
        int sr0 = SCAT ? scatterC[r0] : r0;
        int sr1 = SCAT ? scatterC[r1] : r1;
        #pragma unroll
        for (int nt = 0; nt < 8; nt++) {
            int col = bn + warpN * 64 + nt * 8 + 2 * tg;
            float v0 = alpha * acc[mt][nt][0], v1 = alpha * acc[mt][nt][1];
            float v2 = alpha * acc[mt][nt][2], v3 = alpha * acc[mt][nt][3];
            if (bias) {
                float b0 = bias[col], b1 = bias[col + 1];
                v0 += b0; v1 += b1; v2 += b0; v3 += b1;
            }
            if (OUTH) {
                __half* Ch = (__half*)C;
                *(unsigned*)&Ch[(long)sr0 * ldc + col] = f2h2(v0, v1);
                *(unsigned*)&Ch[(long)sr1 * ldc + col] = f2h2(v2, v3);
            } else {
                *(float2*)&C[(long)sr0 * ldc + col] = make_float2(v0, v1);
                *(float2*)&C[(long)sr1 * ldc + col] = make_float2(v2, v3);
            }
        }
    }
    #undef TLDG
    #undef TST
}

// ============ a3v_gemm: C[NC,64] += softmax(Ah)@B; half A, splitK, atomics, 256 thr ============
__global__ void __launch_bounds__(256) a3v_gemm_kernel(
    const __half* __restrict__ A, int lda, long sA,
    const float* __restrict__ B, int ldb, long sB,
    float* __restrict__ C, int ldc, long sC,
    int K, int splitK, const float2* __restrict__ stats, int Mrows)
{
    __shared__ unsigned As[2][128][20];
    __shared__ unsigned Bs[2][16][72];
    int bz = blockIdx.z;
    int batch = bz / splitK, split = bz - batch * splitK;
    A += (long)batch * sA; B += (long)batch * sB; C += (long)batch * sC;
    int Ks = K / splitK, kbeg = split * Ks, kend = kbeg + Ks;
    int bm = blockIdx.y * 128, bn = blockIdx.x * 64;
    int tid = threadIdx.x, lane = tid & 31, wid = tid >> 5;
    int warpM = wid >> 1, warpN = wid & 1, g = lane >> 2, tg = lane & 3;
    int ar = tid >> 1, ak = (tid & 1) * 8;
    const __half* Ap = A + (long)(bm + ar) * lda + ak;
    float2 ast = stats[(long)batch * Mrows + bm + ar];
    int bk = tid >> 4, bnn = (tid & 15) * 4;   // 16 rows x 16 threads, 4 floats each
    const float* Bp = B + (long)bk * ldb + bn + bnn;
    float aR[8], bR[4];
    float acc[2][4][4];
    #pragma unroll
    for (int i = 0; i < 2; i++)
        #pragma unroll
        for (int j = 0; j < 4; j++)
            #pragma unroll
            for (int l = 0; l < 4; l++) acc[i][j][l] = 0.f;

    #define VLDG(k0) do {                                                      \
        uint4 _av = *(const uint4*)(Ap + (k0));                                \
        const __half* _ah = (const __half*)&_av;                               \
        _Pragma("unroll")                                                      \
        for (int _i = 0; _i < 8; _i++)                                         \
            aR[_i] = __expf(__half2float(_ah[_i]) - ast.x) * ast.y;            \
        float4 _b0 = *(const float4*)(Bp + (long)(k0) * ldb);                  \
        bR[0]=_b0.x; bR[1]=_b0.y; bR[2]=_b0.z; bR[3]=_b0.w;                    \
    } while (0)
    #define VST(p) do {                                                        \
        _Pragma("unroll")                                                      \
        for (int _i = 0; _i < 8; _i++) As[p][ar][ak + _i] = f2tf32(aR[_i]);    \
        _Pragma("unroll")                                                      \
        for (int _i = 0; _i < 4; _i++)                                         \
            Bs[p][bk][bnn + _i] = f2tf32(bR[_i]);                              \
    } while (0)

    VLDG(kbeg); VST(0);
    __syncthreads();
    int buf = 0;
    for (int k0 = kbeg; k0 < kend; k0 += 16) {
        bool nxt = (k0 + 16) < kend;
        if (nxt) VLDG(k0 + 16);
        #pragma unroll
        for (int kk = 0; kk < 16; kk += 8) {
            unsigned af[2][4];
            #pragma unroll
            for (int mt = 0; mt < 2; mt++) {
                int r0 = warpM * 32 + mt * 16;
                af[mt][0] = As[buf][r0 + g    ][kk + tg];
                af[mt][1] = As[buf][r0 + g + 8][kk + tg];
                af[mt][2] = As[buf][r0 + g    ][kk + tg + 4];
                af[mt][3] = As[buf][r0 + g + 8][kk + tg + 4];
            }
            unsigned bf[4][2];
            #pragma unroll
            for (int nt = 0; nt < 4; nt++) {
                int c0 = warpN * 32 + nt * 8;
                bf[nt][0] = Bs[buf][kk + tg    ][c0 + g];
                bf[nt][1] = Bs[buf][kk + tg + 4][c0 + g];
            }
            #pragma unroll
            for (int mt = 0; mt < 2; mt++)
                #pragma unroll
                for (int nt = 0; nt < 4; nt++)
                    mma_tf32(acc[mt][nt], af[mt], bf[nt]);
        }
        if (nxt) { VST(buf ^ 1); __syncthreads(); }
        buf ^= 1;
    }
    #pragma unroll
    for (int mt = 0; mt < 2; mt++) {
        int r0 = bm + warpM * 32 + mt * 16 + g, r1 = r0 + 8;
        #pragma unroll
        for (int nt = 0; nt < 4; nt++) {
            int col = bn + warpN * 32 + nt * 8 + 2 * tg;
            atomicAdd(&C[(long)r0 * ldc + col], acc[mt][nt][0]);
            atomicAdd(&C[(long)r0 * ldc + col + 1], acc[mt][nt][1]);
            atomicAdd(&C[(long)r1 * ldc + col], acc[mt][nt][2]);
            atomicAdd(&C[(long)r1 * ldc + col + 1], acc[mt][nt][3]);
        }
    }
    #undef VLDG
    #undef VST
}

// ============ fused pinv megakernel: 24 GEMM stages, grid barrier ============
template<bool DIAG>
__device__ __forceinline__ void pinv_tile(
    const __half* __restrict__ A, const __half* __restrict__ B, __half* __restrict__ C,
    float alpha, float diagc, int bm, int bn,
    unsigned As[2][128][20], unsigned Bs[2][16][132])
{
    int tid = threadIdx.x, lane = tid & 31, wid = tid >> 5;
    int warpM = wid >> 1, warpN = wid & 1, g = lane >> 2, tg = lane & 3;
    int ar = tid >> 1, akb = (tid & 1) * 16;
    const __half* Ap = A + (long)(bm + ar) * NC + akb;
    int bp2 = tid >> 4, bsn = (tid & 15) * 8;
    const __half* Bp = B + (long)(2 * bp2) * NC + bn + bsn;
    __half dch = __float2half(diagc), zh = __float2half(0.f);

    unsigned aU[8], bU[8];
    float acc[2][8][4];
    #pragma unroll
    for (int i = 0; i < 2; i++)
        #pragma unroll
        for (int j = 0; j < 8; j++)
            #pragma unroll
            for (int l = 0; l < 4; l++) acc[i][j][l] = 0.f;

    #define HLDG(k0) do {                                                      \
        uint4 _a01 = __ldcg((const uint4*)(Ap + (k0)));                        \
        uint4 _a23 = __ldcg((const uint4*)(Ap + (k0) + 8));                    \
        aU[0]=_a01.x; aU[1]=_a01.y; aU[2]=_a01.z; aU[3]=_a01.w;                \
        aU[4]=_a23.x; aU[5]=_a23.y; aU[6]=_a23.z; aU[7]=_a23.w;                \
        uint4 _r0 = __ldcg((const uint4*)(Bp + (long)(k0) * NC));              \
        uint4 _r1 = __ldcg((const uint4*)(Bp + (long)(k0) * NC + NC));         \
        const unsigned short* _h0 = (const unsigned short*)&_r0;               \
        const unsigned short* _h1 = (const unsigned short*)&_r1;               \
        _Pragma("unroll")                                                      \
        for (int _j = 0; _j < 8; _j++)                                         \
            bU[_j] = (unsigned)_h0[_j] | ((unsigned)_h1[_j] << 16);            \
        if (DIAG) {                                                            \
            int _ka = (k0) + 2 * bp2, _kb = _ka + 1, _n = bn + bsn;            \
            _Pragma("unroll")                                                  \
            for (int _j = 0; _j < 8; _j++) {                                   \
                __half2 _d = __halves2half2((_ka == _n + _j) ? dch : zh,       \
                                            (_kb == _n + _j) ? dch : zh);      \
                __half2 _b = *(__half2*)&bU[_j];                               \
                __half2 _o = __hsub2(_d, _b);                                  \
                bU[_j] = *(unsigned*)&_o;                                      \
            }                                                                  \
        }                                                                      \
    } while (0)

    #define HST(p) do {                                                        \
        int _cb = (tid & 1) * 8;                                               \
        _Pragma("unroll")                                                      \
        for (int _j = 0; _j < 4; _j++)                                         \
            *(uint2*)&As[p][ar][_cb + 2 * _j] = make_uint2(aU[_j], aU[_j + 4]);\
        int _t = tid & 15;                                                     \
        _Pragma("unroll")                                                      \
        for (int _j = 0; _j < 8; _j++)                                         \
            Bs[p][bp2][_j * 16 + _t] = bU[_j];                                 \
    } while (0)

    HLDG(0); HST(0);
    __syncthreads();
    int buf = 0;
    for (int k0 = 0; k0 < NC; k0 += 32) {
        bool nxt = (k0 + 32) < NC;
        if (nxt) HLDG(k0 + 32);
        #pragma unroll
        for (int c = 0; c < 2; c++) {
            unsigned af[2][4];
            #pragma unroll
            for (int mt = 0; mt < 2; mt++) {
                int r0 = warpM * 32 + mt * 16;
                uint2 p0 = *(const uint2*)&As[buf][r0 + g    ][c * 8 + 2 * tg];
                uint2 p1 = *(const uint2*)&As[buf][r0 + g + 8][c * 8 + 2 * tg];
                af[mt][0] = p0.x; af[mt][1] = p1.x; af[mt][2] = p0.y; af[mt][3] = p1.y;
            }
            unsigned bf[8][2];
            {
                int s0 = g * 16 + warpN * 8;
                uint4 q0 = *(const uint4*)&Bs[buf][c * 8 + tg    ][s0];
                uint4 q1 = *(const uint4*)&Bs[buf][c * 8 + tg    ][s0 + 4];
                uint4 q2 = *(const uint4*)&Bs[buf][c * 8 + tg + 4][s0];
                uint4 q3 = *(const uint4*)&Bs[buf][c * 8 + tg + 4][s0 + 4];
                bf[0][0]=q0.x; bf[1][0]=q0.y; bf[2][0]=q0.z; bf[3][0]=q0.w;
                bf[4][0]=q1.x; bf[5][0]=q1.y; bf[6][0]=q1.z; bf[7][0]=q1.w;
                bf[0][1]=q2.x; bf[1][1]=q2.y; bf[2][1]=q2.z; bf[3][1]=q2.w;
                bf[4][1]=q3.x; bf[5][1]=q3.y; bf[6][1]=q3.z; bf[7][1]=q3.w;
            }
            #pragma unroll
            for (int mt = 0; mt < 2; mt++)
                #pragma unroll
                for (int nt = 0; nt < 8; nt++)
                    mma_f16(acc[mt][nt], af[mt], bf[nt]);
        }
        if (nxt) { HST(buf ^ 1); __syncthreads(); }
        buf ^= 1;
    }

    #pragma unroll
    for (int mt = 0; mt < 2; mt++) {
        int r0 = bm + warpM * 32 + mt * 16 + g, r1 = r0 + 8;
        #pragma unroll
        for (int nt = 0; nt < 8; nt++) {
            int col = bn + warpN * 64 + nt * 8 + 2 * tg;
            __stcg((unsigned*)&C[(long)r0 * NC + col],
                   f2h2(alpha * acc[mt][nt][0], alpha * acc[mt][nt][1]));
            __stcg((unsigned*)&C[(long)r1 * NC + col],
                   f2h2(alpha * acc[mt][nt][2], alpha * acc[mt][nt][3]));
        }
    }
    #undef HLDG
    #undef HST
}

__global__ void __launch_bounds__(256) pinv_fused_kernel(
    const __half* __restrict__ a2h, __half* __restrict__ xz,
    __half* __restrict__ u1, __half* __restrict__ u2,
    __half* __restrict__ za, __half* __restrict__ zb)
{
    __shared__ unsigned As[2][128][20];
    __shared__ unsigned Bs[2][16][132];
    int bid = blockIdx.x;
    int h = bid >> 4, by = (bid >> 2) & 3, bx = bid & 3;
    int bm = by * 128, bn = bx * 128;
    long off = (long)h * NC * NC;
    unsigned epoch = 0;

    #define GRID_BAR() do {                                                    \
        __threadfence();                                                       \
        __syncthreads();                                                       \
        if (threadIdx.x == 0) {                                                \
            atomicAdd(&g_bar, 1u);                                             \
            epoch += 128;                                                      \
            while (*(volatile unsigned*)&g_bar < epoch) { }                    \
            __threadfence();                                                   \
        }                                                                      \
        __syncthreads();                                                       \
    } while (0)

    __half* zc = za; __half* zn = zb;
    for (int it = 0; it < 6; it++) {
        pinv_tile<false>(a2h + off, zc + off, xz + off, 1.f, 0.f, bm, bn, As, Bs);
        GRID_BAR();
        pinv_tile<true >(xz + off, xz + off, u1 + off, 1.f, 7.f, bm, bn, As, Bs);
        GRID_BAR();
        pinv_tile<true >(xz + off, u1 + off, u2 + off, 1.f, 15.f, bm, bn, As, Bs);
        GRID_BAR();
        pinv_tile<true >(zc + off, u2 + off, zn + off, 0.25f, 13.f, bm, bn, As, Bs);
        if (it != 5) GRID_BAR();
        __half* t = zc; zc = zn; zn = t;
    }
    #undef GRID_BAR
}

// ---------------- sort ----------------
__global__ void init_scalars_kernel() { g_maxcs = 0u; }

__global__ void hist_kernel(const int* __restrict__ labels) {
    __shared__ int sh[NC];
    int t = threadIdx.x;
    sh[t] = 0; sh[t + 256] = 0;
    __syncthreads();
    atomicAdd(&sh[labels[blockIdx.x * 256 + t]], 1);
    __syncthreads();
    g_bh[blockIdx.x * NC + t]       = sh[t];
    g_bh[blockIdx.x * NC + t + 256] = sh[t + 256];
}

__global__ void scan_kernel() {
    __shared__ int s[NC];
    int c = threadIdx.x;
    int tot = 0;
    for (int b = 0; b < 64; b++) { int v = g_bh[b * NC + c]; g_bh[b * NC + c] = tot; tot += v; }
    g_counts[c] = tot; s[c] = tot;
    __syncthreads();
    for (int d = 1; d < NC; d <<= 1) {
        int v = (c >= d) ? s[c - d] : 0;
        __syncthreads(); s[c] += v; __syncthreads();
    }
    int excl = s[c] - tot;
    g_offsets[c] = excl;
    for (int b = 0; b < 64; b++) g_bh[b * NC + c] += excl;
}

__global__ void place_kernel(const int* __restrict__ labels) {
    __shared__ int slab[256];
    int t = threadIdx.x, i = blockIdx.x * 256 + t;
    int c = labels[i];
    slab[t] = c;
    __syncthreads();
    int rank = 0;
    for (int j = 0; j < t; j++) rank += (slab[j] == c);
    g_idx[g_bh[blockIdx.x * NC + c] + rank] = i;
}

__global__ void landmark_kernel() {
    int c = blockIdx.x, h = blockIdx.y, t = threadIdx.x;
    int start = g_offsets[c], cnt = g_counts[c];
    int col = (t < DH) ? (h * DH + t) : (DIM + h * DH + (t - DH));
    float s = 0.f;
    for (int r = 0; r < cnt; r++) s += g_qkv[(long)(start + r) * QKVW + col];
    float m = s / (float)(cnt > 0 ? cnt : 1);
    long o = ((long)h * NC + c) * DH;
    if (t < DH) g_ql[o + t] = m; else g_kl[o + (t - DH)] = m;
}

__global__ void softmax_kernel(float* __restrict__ d, int C) {
    d += blockIdx.x * (long)C;
    __shared__ float red[256];
    int t = threadIdx.x;
    float m = -1e30f;
    for (int i = t; i < C; i += 256) m = fmaxf(m, d[i]);
    red[t] = m; __syncthreads();
    for (int s = 128; s > 0; s >>= 1) { if (t < s) red[t] = fmaxf(red[t], red[t + s]); __syncthreads(); }
    m = red[0]; __syncthreads();
    float sum = 0.f;
    for (int i = t; i < C; i += 256) { float e = expf(d[i] - m); d[i] = e; sum += e; }
    red[t] = sum; __syncthreads();
    for (int s = 128; s > 0; s >>= 1) { if (t < s) red[t] += red[t + s]; __syncthreads(); }
    float inv = 1.f / red[0];
    for (int i = t; i < C; i += 256) d[i] *= inv;
}

// stats over half matrix rows
__global__ void stats_h_kernel(const __half* __restrict__ d, float2* __restrict__ st, int C) {
    long row = blockIdx.x;
    const __half2* d2 = (const __half2*)(d + row * (long)C);
    int C2 = C / 2;
    __shared__ float red[256];
    int t = threadIdx.x;
    float m = -1e30f;
    for (int i = t; i < C2; i += 256) {
        float2 v = __half22float2(d2[i]);
        m = fmaxf(m, fmaxf(v.x, v.y));
    }
    red[t] = m; __syncthreads();
    for (int s = 128; s > 0; s >>= 1) { if (t < s) red[t] = fmaxf(red[t], red[t + s]); __syncthreads(); }
    m = red[0]; __syncthreads();
    float sum = 0.f;
    for (int i = t; i < C2; i += 256) {
        float2 v = __half22float2(d2[i]);
        sum += __expf(v.x - m) + __expf(v.y - m);
    }
    red[t] = sum; __syncthreads();
    for (int s = 128; s > 0; s >>= 1) { if (t < s) red[t] += red[t + s]; __syncthreads(); }
    if (t == 0) st[row] = make_float2(m, 1.f / red[0]);
}

__global__ void colsum_kernel() {
    int h = blockIdx.x, t = threadIdx.x;
    const float* d = g_a2 + (long)h * NC * NC;
    float s0 = 0.f, s1 = 0.f, s2 = 0.f, s3 = 0.f;
    #pragma unroll 4
    for (int r = 0; r < NC; r += 4) {
        s0 += d[(long)r * NC + t];
        s1 += d[(long)(r + 1) * NC + t];
        s2 += d[(long)(r + 2) * NC + t];
        s3 += d[(long)(r + 3) * NC + t];
    }
    float s = (s0 + s1) + (s2 + s3);
    __shared__ float red[512];
    red[t] = s; __syncthreads();
    for (int k = 256; k > 0; k >>= 1) { if (t < k) red[t] = fmaxf(red[t], red[t + k]); __syncthreads(); }
    if (t == 0) atomicMax(&g_maxcs, __float_as_uint(red[0]));
}

__global__ void zinit_kernel() {
    if (blockIdx.x == 0 && threadIdx.x == 0) g_bar = 0u;
    float scale = 1.f / __uint_as_float(g_maxcs);
    long id = (long)blockIdx.x * 256 + threadIdx.x;
    int j = (int)(id & 511), i = (int)((id >> 9) & 511);
    long h = id >> 18;
    g_za[id]  = __float2half(g_a2[(h << 18) + ((long)j << 9) + i] * scale);
    g_a2h[id] = __float2half(g_a2[id]);
}

__global__ void zero_kernel(float* __restrict__ p) {
    p[(long)blockIdx.x * 256 + threadIdx.x] = 0.f;
}

// depthwise conv residual -> PURE STORE into osort (flash1 accumulates on top)
#define CTI 128
__global__ void conv_add_kernel(const float* __restrict__ w_res) {
    __shared__ float sv[CTI + KW - 1][DH];
    __shared__ float w[KW];
    int h = blockIdx.y, i0 = blockIdx.x * CTI, t = threadIdx.x;
    if (t < KW) w[t] = w_res[h * KW + t];
    for (int e = t; e < (CTI + KW - 1) * (DH / 2); e += 256) {
        int r = e >> 5, c2 = e & 31;
        int gi = i0 + r - KW / 2;
        float2 v = make_float2(0.f, 0.f);
        if (gi >= 0 && gi < N_TOK)
            v = *(const float2*)&g_qkv[(long)gi * QKVW + 2 * DIM + h * DH + c2 * 2];
        *(float2*)&sv[r][c2 * 2] = v;
    }
    __syncthreads();
    for (int e = t; e < CTI * (DH / 2); e += 256) {
        int r = e >> 5, c2 = e & 31;
        float2 acc = make_float2(0.f, 0.f);
        #pragma unroll
        for (int k = 0; k < KW; k++) {
            float2 v = *(float2*)&sv[r + k][c2 * 2];
            acc.x += w[k] * v.x; acc.y += w[k] * v.y;
        }
        *(float2*)&g_osort[(long)(i0 + r) * DIM + h * DH + c2 * 2] = acc;
    }
}

// flash1: osort += softmax(q @ kl^T) @ wm (fp16 MMAs, register P)
__global__ void __launch_bounds__(128) flash1_kernel() {
    __shared__ unsigned Ks[64][36];
    __shared__ unsigned Ws[64][36];
    int h = blockIdx.y, bm = blockIdx.x * 64;
    int tid = threadIdx.x, lane = tid & 31, wid = tid >> 5;
    int g = lane >> 2, tg = lane & 3, wr0 = wid * 16;

    for (int e = tid; e < 64 * 8; e += 128) {
        int r = e >> 3, d8 = (e & 7) * 8;
        const float* q = &g_qkv[(long)(bm + r) * QKVW + h * DH + d8];
        float4 v0 = *(const float4*)q, v1 = *(const float4*)(q + 4);
        int c2 = d8 >> 1;
        Ks[r][c2]     = f2h2(v0.x, v0.y);
        Ks[r][c2 + 1] = f2h2(v0.z, v0.w);
        Ks[r][c2 + 2] = f2h2(v1.x, v1.y);
        Ks[r][c2 + 3] = f2h2(v1.z, v1.w);
    }
    __syncthreads();
    unsigned qf[4][4];
    #pragma unroll
    for (int c = 0; c < 4; c++) {
        qf[c][0] = Ks[wr0 + g    ][c * 8 + tg];
        qf[c][1] = Ks[wr0 + g + 8][c * 8 + tg];
        qf[c][2] = Ks[wr0 + g    ][c * 8 + tg + 4];
        qf[c][3] = Ks[wr0 + g + 8][c * 8 + tg + 4];
    }

    float m0 = -1e30f, m1 = -1e30f, l0 = 0.f, l1 = 0.f;
    float O[8][4] = {};
    const float* klb = g_kl + (long)h * NC * DH;
    const float* wmb = g_wm + (long)h * NC * DH;

    for (int jc = 0; jc < NC; jc += 64) {
        __syncthreads();
        for (int e = tid; e < 64 * 8; e += 128) {
            int n = e >> 3, d8 = (e & 7) * 8;
            const float* kp = &klb[(long)(jc + n) * DH + d8];
            float4 v0 = *(const float4*)kp, v1 = *(const float4*)(kp + 4);
            int c2 = d8 >> 1;
            Ks[n][c2]     = f2h2(v0.x, v0.y);
            Ks[n][c2 + 1] = f2h2(v0.z, v0.w);
            Ks[n][c2 + 2] = f2h2(v1.x, v1.y);
            Ks[n][c2 + 3] = f2h2(v1.z, v1.w);
        }
        for (int e = tid; e < 32 * 16; e += 128) {
            int j2 = e >> 4, d4 = (e & 15) * 4;
            const float* w0 = &wmb[(long)(jc + 2 * j2) * DH + d4];
            const float* w1 = w0 + DH;
            float4 a = *(const float4*)w0, b = *(const float4*)w1;
            Ws[d4 + 0][j2] = f2h2(a.x, b.x);
            Ws[d4 + 1][j2] = f2h2(a.y, b.y);
            Ws[d4 + 2][j2] = f2h2(a.z, b.z);
            Ws[d4 + 3][j2] = f2h2(a.w, b.w);
        }
        __syncthreads();

        float s[8][4] = {};
        #pragma unroll
        for (int c = 0; c < 4; c++) {
            #pragma unroll
            for (int nt = 0; nt < 8; nt++) {
                unsigned bf[2];
                bf[0] = Ks[nt * 8 + g][c * 8 + tg];
                bf[1] = Ks[nt * 8 + g][c * 8 + tg + 4];
                mma_f16(s[nt], qf[c], bf);
            }
        }

        float mc0 = -1e30f, mc1 = -1e30f;
        #pragma unroll
        for (int nt = 0; nt < 8; nt++) {
            mc0 = fmaxf(mc0, fmaxf(s[nt][0], s[nt][1]));
            mc1 = fmaxf(mc1, fmaxf(s[nt][2], s[nt][3]));
        }
        mc0 = fmaxf(mc0, __shfl_xor_sync(~0u, mc0, 1));
        mc0 = fmaxf(mc0, __shfl_xor_sync(~0u, mc0, 2));
        mc1 = fmaxf(mc1, __shfl_xor_sync(~0u, mc1, 1));
        mc1 = fmaxf(mc1, __shfl_xor_sync(~0u, mc1, 2));
        float mn0 = fmaxf(m0, mc0), mn1 = fmaxf(m1, mc1);
        float sc0 = __expf(m0 - mn0), sc1 = __expf(m1 - mn1);
        float ps0 = 0.f, ps1 = 0.f;
        float p[8][4];
        #pragma unroll
        for (int nt = 0; nt < 8; nt++) {
            p[nt][0] = __expf(s[nt][0] - mn0);
            p[nt][1] = __expf(s[nt][1] - mn0);
            p[nt][2] = __expf(s[nt][2] - mn1);
            p[nt][3] = __expf(s[nt][3] - mn1);
            ps0 += p[nt][0] + p[nt][1];
            ps1 += p[nt][2] + p[nt][3];
            O[nt][0] *= sc0; O[nt][1] *= sc0; O[nt][2] *= sc1; O[nt][3] *= sc1;
        }
        ps0 += __shfl_xor_sync(~0u, ps0, 1); ps0 += __shfl_xor_sync(~0u, ps0, 2);
        ps1 += __shfl_xor_sync(~0u, ps1, 1); ps1 += __shfl_xor_sync(~0u, ps1, 2);
        l0 = l0 * sc0 + ps0; l1 = l1 * sc1 + ps1;
        m0 = mn0; m1 = mn1;

        unsigned pf[4][4];
        #pragma unroll
        for (int c = 0; c < 4; c++) {
            pf[c][0] = f2h2(p[2*c][0],   p[2*c][1]);
            pf[c][1] = f2h2(p[2*c][2],   p[2*c][3]);
            pf[c][2] = f2h2(p[2*c+1][0], p[2*c+1][1]);
            pf[c][3] = f2h2(p[2*c+1][2], p[2*c+1][3]);
        }
        #pragma unroll
        for (int c = 0; c < 4; c++) {
            #pragma unroll
            for (int nt = 0; nt < 8; nt++) {
                unsigned bf[2];
                bf[0] = Ws[nt * 8 + g][c * 8 + tg];
                bf[1] = Ws[nt * 8 + g][c * 8 + tg + 4];
                mma_f16(O[nt], pf[c], bf);
            }
        }
    }

    float inv0 = 1.f / l0, inv1 = 1.f / l1;
    int r0 = bm + wr0 + g, r1 = r0 + 8;
    #pragma unroll
    for (int nt = 0; nt < 8; nt++) {
        int col = h * DH + nt * 8 + 2 * tg;
        float2* o0 = (float2*)&g_osort[(long)r0 * DIM + col];
        float2* o1 = (float2*)&g_osort[(long)r1 * DIM + col];
        float2 c0 = *o0, c1 = *o1;
        *o0 = make_float2(c0.x + O[nt][0] * inv0, c0.y + O[nt][1] * inv0);
        *o1 = make_float2(c1.x + O[nt][2] * inv1, c1.y + O[nt][3] * inv1);
    }
}

// ---------------- small GEMM (wm = z @ a3v): half A, fp32 B/C, tf32 MMA, 128 thr ----------------
__global__ void __launch_bounds__(128) small_gemm_kernel(
    const __half* __restrict__ A, int lda, long sA,
    const float* __restrict__ B, int ldb, long sB,
    float* __restrict__ C, int ldc, long sC, int K)
{
    __shared__ unsigned As[2][64][20];
    __shared__ unsigned Bs[2][16][72];
    int z = blockIdx.z;
    A += (long)z * sA; B += (long)z * sB; C += (long)z * sC;
    int bm = blockIdx.y * 64, bn = blockIdx.x * 64;
    int tid = threadIdx.x, lane = tid & 31, wid = tid >> 5;
    int warpM = wid >> 1, warpN = wid & 1, g = lane >> 2, tg = lane & 3;
    int ar = tid >> 1, ak = (tid & 1) * 8;
    const __half* Ap = A + (long)(bm + ar) * lda + ak;
    int bk = tid >> 4, bnn = (tid & 15) * 4;
    const float* Bp = B + (long)bk * ldb + bn + bnn;
    float aR[8], bR[8];
    float acc[2][4][4] = {};

    #define SLDG(k0) do {                                                      \
        uint4 _av = __ldcg((const uint4*)(Ap + (k0)));                         \
        const __half* _ah = (const __half*)&_av;                               \
        _Pragma("unroll")                                                      \
        for (int _i = 0; _i < 8; _i++) aR[_i] = __half2float(_ah[_i]);         \
        float4 _b0 = *(const float4*)(Bp + (long)(k0) * ldb);                  \
        float4 _b1 = *(const float4*)(Bp + (long)((k0) + 8) * ldb);            \
        bR[0]=_b0.x; bR[1]=_b0.y; bR[2]=_b0.z; bR[3]=_b0.w;                    \
        bR[4]=_b1.x; bR[5]=_b1.y; bR[6]=_b1.z; bR[7]=_b1.w;                    \
    } while (0)
    #define SST(p) do {                                                        \
        _Pragma("unroll")                                                      \
        for (int _i = 0; _i < 8; _i++) As[p][ar][ak + _i] = f2tf32(aR[_i]);    \
        _Pragma("unroll")                                                      \
        for (int _i = 0; _i < 4; _i++) {                                       \
            Bs[p][bk][bnn + _i] = f2tf32(bR[_i]);                              \
            Bs[p][bk + 8][bnn + _i] = f2tf32(bR[4 + _i]);                      \
        }                                                                      \
    } while (0)

    SLDG(0); SST(0);
    __syncthreads();
    int buf = 0;
    for (int k0 = 0; k0 < K; k0 += 16) {
        bool nxt = (k0 + 16) < K;
        if (nxt) SLDG(k0 + 16);
        #pragma unroll
        for (int kk = 0; kk < 16; kk += 8) {
            unsigned af[2][4];
            #pragma unroll
            for (int mt = 0; mt < 2; mt++) {
                int r0 = warpM * 32 + mt * 16;
                af[mt][0] = As[buf][r0 + g    ][kk + tg];
                af[mt][1] = As[buf][r0 + g + 8][kk + tg];
                af[mt][2] = As[buf][r0 + g    ][kk + tg + 4];
                af[mt][3] = As[buf][r0 + g + 8][kk + tg + 4];
            }
            unsigned bf[4][2];
            #pragma unroll
            for (int nt = 0; nt < 4; nt++) {
                int c0 = warpN * 32 + nt * 8;
                bf[nt][0] = Bs[buf][kk + tg    ][c0 + g];
                bf[nt][1] = Bs[buf][kk + tg + 4][c0 + g];
            }
            #pragma unroll
            for (int mt = 0; mt < 2; mt++)
                #pragma unroll
                for (int nt = 0; nt < 4; nt++)
                    mma_tf32(acc[mt][nt], af[mt], bf[nt]);
        }
        if (nxt) { SST(buf ^ 1); __syncthreads(); }
        buf ^= 1;
    }
    #pragma unroll
    for (int mt = 0; mt < 2; mt++) {
        int r0 = bm + warpM * 32 + mt * 16 + g, r1 = r0 + 8;
        #pragma unroll
        for (int nt = 0; nt < 4; nt++) {
            int col = bn + warpN * 32 + nt * 8 + 2 * tg;
            *(float2*)&C[(long)r0 * ldc + col] = make_float2(acc[mt][nt][0], acc[mt][nt][1]);
            *(float2*)&C[(long)r1 * ldc + col] = make_float2(acc[mt][nt][2], acc[mt][nt][3]);
        }
    }
    #undef SLDG
    #undef SST
}

// ---------------- BM=128 tf32 GEMM (a2 only: ql @ kl^T) ----------------
__global__ void __launch_bounds__(256) a2_gemm_kernel(
    const float* __restrict__ A, const float* __restrict__ B, float* __restrict__ C)
{
    __shared__ unsigned As[2][128][20];
    __shared__ unsigned Bs[2][16][136];
    long SL = (long)NC * DH, S2 = (long)NC * NC;
    int batch = blockIdx.z;
    A += batch * SL; B += batch * SL; C += batch * S2;
    int bm = blockIdx.y * 128, bn = blockIdx.x * 128;
    int tid = threadIdx.x, lane = tid & 31, wid = tid >> 5;
    int warpM = wid >> 1, warpN = wid & 1, g = lane >> 2, tg = lane & 3;
    int ar = tid >> 1, ak = (tid & 1) * 8;
    const float* Ap = A + (long)(bm + ar) * DH + ak;
    int bnn = tid >> 1, bk = (tid & 1) * 8;
    const float* Bp = B + (long)(bn + bnn) * DH + bk;
    float aR[8], bR[8];
    float acc[2][8][4];
    #pragma unroll
    for (int i = 0; i < 2; i++)
        #pragma unroll
        for (int j = 0; j < 8; j++)
            #pragma unroll
            for (int l = 0; l < 4; l++) acc[i][j][l] = 0.f;

    #define ALDG(k0) do {                                                      \
        float4 _a0 = *(const float4*)(Ap + (k0));                              \
        float4 _a1 = *(const float4*)(Ap + (k0) + 4);                          \
        aR[0]=_a0.x; aR[1]=_a0.y; aR[2]=_a0.z; aR[3]=_a0.w;                    \
        aR[4]=_a1.x; aR[5]=_a1.y; aR[6]=_a1.z; aR[7]=_a1.w;                    \
        float4 _b0 = *(const float4*)(Bp + (k0));                              \
        float4 _b1 = *(const float4*)(Bp + (k0) + 4);                          \
        bR[0]=_b0.x; bR[1]=_b0.y; bR[2]=_b0.z; bR[3]=_b0.w;                    \
        bR[4]=_b1.x; bR[5]=_b1.y; bR[6]=_b1.z; bR[7]=_b1.w;                    \
    } while (0)
    #define AST(p) do {                                                        \
        _Pragma("unroll")                                                      \
        for (int _i = 0; _i < 8; _i++) As[p][ar][ak + _i] = f2tf32(aR[_i]);    \
        _Pragma("unroll")                                                      \
        for (int _i = 0; _i < 8; _i++) Bs[p][bk + _i][bnn] = f2tf32(bR[_i]);   \
    } while (0)

    ALDG(0); AST(0);
    __syncthreads();
    int buf = 0;
    for (int k0 = 0; k0 < DH; k0 += 16) {
        bool nxt = (k0 + 16) < DH;
        if (nxt) ALDG(k0 + 16);
        #pragma unroll
        for (int kk = 0; kk < 16; kk += 8) {
            unsigned af[2][4];
            #pragma unroll
            for (int mt = 0; mt < 2; mt++) {
                int r0 = warpM * 32 + mt * 16;
                af[mt][0] = As[buf][r0 + g    ][kk + tg];
                af[mt][1] = As[buf][r0 + g + 8][kk + tg];
                af[mt][2] = As[buf][r0 + g    ][kk + tg + 4];
                af[mt][3] = As[buf][r0 + g + 8][kk + tg + 4];
            }
            unsigned bf[8][2];
            #pragma unroll
            for (int nt = 0; nt < 8; nt++) {
                int c0 = warpN * 64 + nt * 8;
                bf[nt][0] = Bs[buf][kk + tg    ][c0 + g];
                bf[nt][1] = Bs[buf][kk + tg + 4][c0 + g];
            }
            #pragma unroll
            for (int mt = 0; mt < 2; mt++)
                #pragma unroll
                for (int nt = 0; nt < 8; nt++)
                    mma_tf32(acc[mt][nt], af[mt], bf[nt]);
        }
        if (nxt) { AST(buf ^ 1); __syncthreads(); }
        buf ^= 1;
    }
    #pragma unroll
    for (int mt = 0; mt < 2; mt++) {
        int r0 = bm + warpM * 32 + mt * 16 + g, r1 = r0 + 8;
        #pragma unroll
        for (int nt = 0; nt < 8; nt++) {
            int col = bn + warpN * 64 + nt * 8 + 2 * tg;
            *(float2*)&C[(long)r0 * NC + col] = make_float2(acc[mt][nt][0], acc[mt][nt][1]);
            *(float2*)&C[(long)r1 * NC + col] = make_float2(acc[mt][nt][2], acc[mt][nt][3]);
        }
    }
    #undef ALDG
    #undef AST
}

extern "C" void kernel_launch(void* const* d_in, const int* in_sizes, int n_in,
                              void* d_out, int out_size)
{
    const float* x      = (const float*)d_in[0];
    const int*   labels = (const int*)  d_in[1];
    const float* w_qkv  = (const float*)d_in[2];
    const float* w_res  = (const float*)d_in[3];
    const float* w_out  = (const float*)d_in[4];
    const float* b_out  = (const float*)d_in[5];
    float* out = (float*)d_out;

    float *qkv, *a2, *ql, *kl, *a3v, *wm, *osort;
    __half *sim3, *a2h, *xz, *u1, *u2, *za, *zb;
    float2 *st3;
    int* idx;
    cudaGetSymbolAddress((void**)&qkv,  g_qkv);
    cudaGetSymbolAddress((void**)&sim3, g_sim3);
    cudaGetSymbolAddress((void**)&a2,   g_a2);
    cudaGetSymbolAddress((void**)&a2h,  g_a2h);
    cudaGetSymbolAddress((void**)&xz,   g_xz);
    cudaGetSymbolAddress((void**)&u1,   g_u1);
    cudaGetSymbolAddress((void**)&u2,   g_u2);
    cudaGetSymbolAddress((void**)&za,   g_za);
    cudaGetSymbolAddress((void**)&zb,   g_zb);
    cudaGetSymbolAddress((void**)&ql,   g_ql);
    cudaGetSymbolAddress((void**)&kl,   g_kl);
    cudaGetSymbolAddress((void**)&a3v,  g_a3v);
    cudaGetSymbolAddress((void**)&wm,   g_wm);
    cudaGetSymbolAddress((void**)&osort,g_osort);
    cudaGetSymbolAddress((void**)&st3,  g_st3);
    cudaGetSymbolAddress((void**)&idx,  g_idx);

    static cudaStream_t s2 = nullptr;
    static cudaEvent_t evS = nullptr, evL = nullptr, evJ = nullptr;
    if (!s2) {
        cudaStreamCreateWithFlags(&s2, cudaStreamNonBlocking);
        cudaEventCreateWithFlags(&evS, cudaEventDisableTiming);
        cudaEventCreateWithFlags(&evL, cudaEventDisableTiming);
        cudaEventCreateWithFlags(&evJ, cudaEventDisableTiming);
    }

    const long S2 = (long)NC * NC;
    const long SL = (long)NC * DH;
    const long ST3 = (long)NC * N_TOK;   // half elements per head

    // sort
    init_scalars_kernel<<<1, 1>>>();
    hist_kernel <<<64, 256>>>(labels);
    scan_kernel <<<1, 512>>>();
    place_kernel<<<64, 256>>>(labels);
    cudaEventRecord(evS, 0);

    // qk = x[idx] @ w_qkv[0:1024]^T (serial); v on s2
    tt_gemm<true, false, false><<<dim3(1024 / 128, N_TOK / 128, 1), 256>>>(
        x, DIM, 0, w_qkv, DIM, 0, qkv, QKVW, 0, DIM, 1.f, idx, nullptr, nullptr);

    landmark_kernel<<<dim3(NC, NH), 128>>>();
    cudaEventRecord(evL, 0);

    // --- s2 branch: v GEMM -> sim3 (half) -> stats -> a3v -> conv ---
    cudaStreamWaitEvent(s2, evS, 0);
    tt_gemm<true, false, false><<<dim3(512 / 128, N_TOK / 128, 1), 256, 0, s2>>>(
        x, DIM, 0, w_qkv + (long)1024 * DIM, DIM, 0, qkv + 1024, QKVW, 0,
        DIM, 1.f, idx, nullptr, nullptr);
    cudaStreamWaitEvent(s2, evL, 0);
    tt_gemm<true, false, true><<<dim3(N_TOK / 128, NC / 128, NH), 256, 0, s2>>>(
        ql, DH, SL, qkv + DIM, QKVW, 64, (float*)sim3, N_TOK, ST3 / 2, DH, 1.f,
        nullptr, nullptr, nullptr);
    stats_h_kernel<<<NH * NC, 256, 0, s2>>>(sim3, st3, N_TOK);
    zero_kernel<<<(NH * NC * DH) / 256, 256, 0, s2>>>(a3v);
    a3v_gemm_kernel<<<dim3(DH / 64, NC / 128, NH * 8), 256, 0, s2>>>(
        sim3, N_TOK, ST3, qkv + 2 * DIM, QKVW, 64, a3v, DH, SL, N_TOK, 8, st3, NC);
    conv_add_kernel<<<dim3(N_TOK / CTI, NH), 256, 0, s2>>>(w_res);
    cudaEventRecord(evJ, s2);

    // --- main branch: a2 + fused pinv ---
    a2_gemm_kernel<<<dim3(NC / 128, NC / 128, NH), 256>>>(ql, kl, a2);
    softmax_kernel<<<NH * NC, 256>>>(a2, NC);
    colsum_kernel<<<NH, 512>>>();
    zinit_kernel<<<(NH * NC * NC) / 256, 256>>>();

    pinv_fused_kernel<<<128, 256>>>(a2h, xz, u1, u2, za, zb);

    // join: wm needs a3v (s2); flash1 needs conv-written osort (s2)
    cudaStreamWaitEvent(0, evJ, 0);
    small_gemm_kernel<<<dim3(1, NC / 64, NH), 128>>>(za, NC, S2, a3v, DH, SL, wm, DH, SL, NC);

    flash1_kernel<<<dim3(N_TOK / 64, NH), 128>>>();

    // output projection + bias + scatter
    tt_gemm<true, true, false><<<dim3(DIM / 128, N_TOK / 128, 1), 256>>>(
        osort, DIM, 0, w_out, DIM, 0, out, DIM, 0, DIM, 1.f, nullptr, idx, b_out);
}

// round 17
// speedup vs baseline: 1.7368x; 1.0029x over previous
#include <cuda_runtime.h>
#include <cuda_fp16.h>
#include <math.h>

#define N_TOK 16384
#define DIM   512
#define NH    8
#define DH    64
#define NC    512
#define QKVW  1536
#define KW    33

__device__ float  g_qkv [(long)N_TOK*QKVW];
__device__ __half g_sim3[(long)NH*NC*N_TOK];
__device__ float  g_a2  [NH*NC*NC];
__device__ __half g_a2h [NH*NC*NC];
__device__ __half g_xz  [NH*NC*NC];
__device__ __half g_u1  [NH*NC*NC];
__device__ __half g_u2  [NH*NC*NC];
__device__ __half g_za  [NH*NC*NC];
__device__ __half g_zb  [NH*NC*NC];
__device__ float  g_ql  [NH*NC*DH];
__device__ float  g_kl  [NH*NC*DH];
__device__ float  g_a3v [NH*NC*DH];
__device__ float  g_wm  [NH*NC*DH];
__device__ float  g_osort[(long)N_TOK*DIM];
__device__ float2 g_st3[NH*NC];
__device__ int    g_idx [N_TOK];
__device__ int    g_counts [NC];
__device__ int    g_offsets[NC];
__device__ int    g_bh[64*NC];
__device__ unsigned g_maxcs;
__device__ unsigned g_bar;

__device__ __forceinline__ unsigned f2tf32(float v) {
    unsigned r; asm("cvt.rna.tf32.f32 %0, %1;" : "=r"(r) : "f"(v)); return r;
}
__device__ __forceinline__ void mma_tf32(float* c, const unsigned* a, const unsigned* b) {
    asm volatile("mma.sync.aligned.m16n8k8.row.col.f32.tf32.tf32.f32 "
        "{%0,%1,%2,%3}, {%4,%5,%6,%7}, {%8,%9}, {%0,%1,%2,%3};"
        : "+f"(c[0]), "+f"(c[1]), "+f"(c[2]), "+f"(c[3])
        : "r"(a[0]), "r"(a[1]), "r"(a[2]), "r"(a[3]), "r"(b[0]), "r"(b[1]));
}
__device__ __forceinline__ unsigned f2h2(float a, float b) {
    __half2 h = __floats2half2_rn(a, b);
    return *(unsigned*)&h;
}
__device__ __forceinline__ void mma_f16(float* c, const unsigned* a, const unsigned* b) {
    asm volatile("mma.sync.aligned.m16n8k16.row.col.f32.f16.f16.f32 "
        "{%0,%1,%2,%3}, {%4,%5,%6,%7}, {%8,%9}, {%0,%1,%2,%3};"
        : "+f"(c[0]), "+f"(c[1]), "+f"(c[2]), "+f"(c[3])
        : "r"(a[0]), "r"(a[1]), "r"(a[2]), "r"(a[3]), "r"(b[0]), "r"(b[1]));
}

// ============ tt_gemm (fp32 in, fp16 MMA): 128x128 tile, 256 thr, K-chunk 32 ============
// OUTH: C is __half (pass sC in float-elems = half-elems/2; ldc in half elems)
template<bool TB, bool SCAT, bool OUTH>
__global__ void __launch_bounds__(256) tt_gemm(
    const float* __restrict__ A, int lda, long sA,
    const float* __restrict__ B, int ldb, long sB,
    float* __restrict__ C, int ldc, long sC,
    int K, float alpha,
    const int* __restrict__ gatherA, const int* __restrict__ scatterC,
    const float* __restrict__ bias)
{
    __shared__ unsigned As[2][128][20];
    __shared__ unsigned Bs[2][16][132];
    int h = blockIdx.z;
    A += (long)h * sA; B += (long)h * sB; C += (long)h * sC;
    int bm = blockIdx.y * 128, bn = blockIdx.x * 128;
    int tid = threadIdx.x, lane = tid & 31, wid = tid >> 5;
    int warpM = wid >> 1, warpN = wid & 1, g = lane >> 2, tg = lane & 3;

    int ar = tid >> 1, akb = (tid & 1) * 16;
    int grow = bm + ar;
    if (gatherA) grow = gatherA[grow];
    const float* Ap = A + (long)grow * lda + akb;

    const float* Bp;
    int bsn = 0, bsk = 0, bp2 = 0;
    if (TB) { bsn = tid >> 1; bsk = (tid & 1) * 16;
              Bp = B + (long)(bn + bsn) * ldb + bsk; }
    else    { bp2 = tid >> 4; bsn = (tid & 15) * 8;
              Bp = B + (long)(2 * bp2) * ldb + bn + bsn; }

    float aR[16], bR[16];
    float acc[2][8][4];
    #pragma unroll
    for (int i = 0; i < 2; i++)
        #pragma unroll
        for (int j = 0; j < 8; j++)
            #pragma unroll
            for (int l = 0; l < 4; l++) acc[i][j][l] = 0.f;

    #define TLDG(k0) do {                                                      \
        float4 _a0 = *(const float4*)(Ap + (k0));                              \
        float4 _a1 = *(const float4*)(Ap + (k0) + 4);                          \
        float4 _a2 = *(const float4*)(Ap + (k0) + 8);                          \
        float4 _a3 = *(const float4*)(Ap + (k0) + 12);                         \
        aR[0]=_a0.x; aR[1]=_a0.y; aR[2]=_a0.z; aR[3]=_a0.w;                    \
        aR[4]=_a1.x; aR[5]=_a1.y; aR[6]=_a1.z; aR[7]=_a1.w;                    \
        aR[8]=_a2.x; aR[9]=_a2.y; aR[10]=_a2.z; aR[11]=_a2.w;                  \
        aR[12]=_a3.x; aR[13]=_a3.y; aR[14]=_a3.z; aR[15]=_a3.w;                \
        if (TB) {                                                              \
            float4 _b0 = *(const float4*)(Bp + (k0));                          \
            float4 _b1 = *(const float4*)(Bp + (k0) + 4);                      \
            float4 _b2 = *(const float4*)(Bp + (k0) + 8);                      \
            float4 _b3 = *(const float4*)(Bp + (k0) + 12);                     \
            bR[0]=_b0.x; bR[1]=_b0.y; bR[2]=_b0.z; bR[3]=_b0.w;                \
            bR[4]=_b1.x; bR[5]=_b1.y; bR[6]=_b1.z; bR[7]=_b1.w;                \
            bR[8]=_b2.x; bR[9]=_b2.y; bR[10]=_b2.z; bR[11]=_b2.w;              \
            bR[12]=_b3.x; bR[13]=_b3.y; bR[14]=_b3.z; bR[15]=_b3.w;            \
        } else {                                                               \
            const float* _r0 = Bp + (long)(k0) * ldb;                          \
            const float* _r1 = _r0 + ldb;                                      \
            float4 _x0 = *(const float4*)(_r0);                                \
            float4 _x1 = *(const float4*)(_r0 + 4);                            \
            float4 _y0 = *(const float4*)(_r1);                                \
            float4 _y1 = *(const float4*)(_r1 + 4);                            \
            bR[0]=_x0.x; bR[1]=_x0.y; bR[2]=_x0.z; bR[3]=_x0.w;                \
            bR[4]=_x1.x; bR[5]=_x1.y; bR[6]=_x1.z; bR[7]=_x1.w;                \
            bR[8]=_y0.x; bR[9]=_y0.y; bR[10]=_y0.z; bR[11]=_y0.w;              \
            bR[12]=_y1.x; bR[13]=_y1.y; bR[14]=_y1.z; bR[15]=_y1.w;            \
        }                                                                      \
    } while (0)

    #define TST(p) do {                                                        \
        int _cb = (tid & 1) * 8;                                               \
        _Pragma("unroll")                                                      \
        for (int _j = 0; _j < 4; _j++)                                         \
            *(uint2*)&As[p][ar][_cb + 2 * _j] = make_uint2(                    \
                f2h2(aR[2*_j], aR[2*_j+1]), f2h2(aR[2*_j+8], aR[2*_j+9]));     \
        if (TB) {                                                              \
            int _kb2 = (tid & 1) * 8, _s = (bsn & 7) * 16 + (bsn >> 3);        \
            _Pragma("unroll")                                                  \
            for (int _j = 0; _j < 8; _j++)                                     \
                Bs[p][_kb2 + _j][_s] = f2h2(bR[2*_j], bR[2*_j+1]);             \
        } else {                                                               \
            int _t = tid & 15;                                                 \
            _Pragma("unroll")                                                  \
            for (int _j = 0; _j < 8; _j++)                                     \
                Bs[p][bp2][_j * 16 + _t] = f2h2(bR[_j], bR[8 + _j]);           \
        }                                                                      \
    } while (0)

    TLDG(0); TST(0);
    __syncthreads();
    int buf = 0;
    for (int k0 = 0; k0 < K; k0 += 32) {
        bool nxt = (k0 + 32) < K;
        if (nxt) TLDG(k0 + 32);
        #pragma unroll
        for (int c = 0; c < 2; c++) {
            unsigned af[2][4];
            #pragma unroll
            for (int mt = 0; mt < 2; mt++) {
                int r0 = warpM * 32 + mt * 16;
                uint2 p0 = *(const uint2*)&As[buf][r0 + g    ][c * 8 + 2 * tg];
                uint2 p1 = *(const uint2*)&As[buf][r0 + g + 8][c * 8 + 2 * tg];
                af[mt][0] = p0.x; af[mt][1] = p1.x; af[mt][2] = p0.y; af[mt][3] = p1.y;
            }
            unsigned bf[8][2];
            {
                int s0 = g * 16 + warpN * 8;
                uint4 q0 = *(const uint4*)&Bs[buf][c * 8 + tg    ][s0];
                uint4 q1 = *(const uint4*)&Bs[buf][c * 8 + tg    ][s0 + 4];
                uint4 q2 = *(const uint4*)&Bs[buf][c * 8 + tg + 4][s0];
                uint4 q3 = *(const uint4*)&Bs[buf][c * 8 + tg + 4][s0 + 4];
                bf[0][0]=q0.x; bf[1][0]=q0.y; bf[2][0]=q0.z; bf[3][0]=q0.w;
                bf[4][0]=q1.x; bf[5][0]=q1.y; bf[6][0]=q1.z; bf[7][0]=q1.w;
                bf[0][1]=q2.x; bf[1][1]=q2.y; bf[2][1]=q2.z; bf[3][1]=q2.w;
                bf[4][1]=q3.x; bf[5][1]=q3.y; bf[6][1]=q3.z; bf[7][1]=q3.w;
            }
            #pragma unroll
            for (int mt = 0; mt < 2; mt++)
                #pragma unroll
                for (int nt = 0; nt < 8; nt++)
                    mma_f16(acc[mt][nt], af[mt], bf[nt]);
        }
        if (nxt) { TST(buf ^ 1); __syncthreads(); }
        buf ^= 1;
    }

    #pragma unroll
    for (int mt = 0; mt < 2; mt++) {
        int r0 = bm + warpM * 32 + mt * 16 + g, r1 = r0 + 8;
        int sr0 = SCAT ? scatterC[r0] : r0;
        int sr1 = SCAT ? scatterC[r1] : r1;
        #pragma unroll
        for (int nt = 0; nt < 8; nt++) {
            int col = bn + warpN * 64 + nt * 8 + 2 * tg;
            float v0 = alpha * acc[mt][nt][0], v1 = alpha * acc[mt][nt][1];
            float v2 = alpha * acc[mt][nt][2], v3 = alpha * acc[mt][nt][3];
            if (bias) {
                float b0 = bias[col], b1 = bias[col + 1];
                v0 += b0; v1 += b1; v2 += b0; v3 += b1;
            }
            if (OUTH) {
                __half* Ch = (__half*)C;
                *(unsigned*)&Ch[(long)sr0 * ldc + col] = f2h2(v0, v1);
                *(unsigned*)&Ch[(long)sr1 * ldc + col] = f2h2(v2, v3);
            } else {
                *(float2*)&C[(long)sr0 * ldc + col] = make_float2(v0, v1);
                *(float2*)&C[(long)sr1 * ldc + col] = make_float2(v2, v3);
            }
        }
    }
    #undef TLDG
    #undef TST
}

// ============ a3v_gemm: C[NC,64] += softmax(Ah)@B; half A, splitK, atomics, 256 thr ============
__global__ void __launch_bounds__(256) a3v_gemm_kernel(
    const __half* __restrict__ A, int lda, long sA,
    const float* __restrict__ B, int ldb, long sB,
    float* __restrict__ C, int ldc, long sC,
    int K, int splitK, const float2* __restrict__ stats, int Mrows)
{
    __shared__ unsigned As[2][128][20];
    __shared__ unsigned Bs[2][16][72];
    int bz = blockIdx.z;
    int batch = bz / splitK, split = bz - batch * splitK;
    A += (long)batch * sA; B += (long)batch * sB; C += (long)batch * sC;
    int Ks = K / splitK, kbeg = split * Ks, kend = kbeg + Ks;
    int bm = blockIdx.y * 128, bn = blockIdx.x * 64;
    int tid = threadIdx.x, lane = tid & 31, wid = tid >> 5;
    int warpM = wid >> 1, warpN = wid & 1, g = lane >> 2, tg = lane & 3;
    int ar = tid >> 1, ak = (tid & 1) * 8;
    const __half* Ap = A + (long)(bm + ar) * lda + ak;
    float2 ast = stats[(long)batch * Mrows + bm + ar];
    int bk = tid >> 4, bnn = (tid & 15) * 4;
    const float* Bp = B + (long)bk * ldb + bn + bnn;
    float aR[8], bR[4];
    float acc[2][4][4];
    #pragma unroll
    for (int i = 0; i < 2; i++)
        #pragma unroll
        for (int j = 0; j < 4; j++)
            #pragma unroll
            for (int l = 0; l < 4; l++) acc[i][j][l] = 0.f;

    #define VLDG(k0) do {                                                      \
        uint4 _av = *(const uint4*)(Ap + (k0));                                \
        const __half* _ah = (const __half*)&_av;                               \
        _Pragma("unroll")                                                      \
        for (int _i = 0; _i < 8; _i++)                                         \
            aR[_i] = __expf(__half2float(_ah[_i]) - ast.x) * ast.y;            \
        float4 _b0 = *(const float4*)(Bp + (long)(k0) * ldb);                  \
        bR[0]=_b0.x; bR[1]=_b0.y; bR[2]=_b0.z; bR[3]=_b0.w;                    \
    } while (0)
    #define VST(p) do {                                                        \
        _Pragma("unroll")                                                      \
        for (int _i = 0; _i < 8; _i++) As[p][ar][ak + _i] = f2tf32(aR[_i]);    \
        _Pragma("unroll")                                                      \
        for (int _i = 0; _i < 4; _i++)                                         \
            Bs[p][bk][bnn + _i] = f2tf32(bR[_i]);                              \
    } while (0)

    VLDG(kbeg); VST(0);
    __syncthreads();
    int buf = 0;
    for (int k0 = kbeg; k0 < kend; k0 += 16) {
        bool nxt = (k0 + 16) < kend;
        if (nxt) VLDG(k0 + 16);
        #pragma unroll
        for (int kk = 0; kk < 16; kk += 8) {
            unsigned af[2][4];
            #pragma unroll
            for (int mt = 0; mt < 2; mt++) {
                int r0 = warpM * 32 + mt * 16;
                af[mt][0] = As[buf][r0 + g    ][kk + tg];
                af[mt][1] = As[buf][r0 + g + 8][kk + tg];
                af[mt][2] = As[buf][r0 + g    ][kk + tg + 4];
                af[mt][3] = As[buf][r0 + g + 8][kk + tg + 4];
            }
            unsigned bf[4][2];
            #pragma unroll
            for (int nt = 0; nt < 4; nt++) {
                int c0 = warpN * 32 + nt * 8;
                bf[nt][0] = Bs[buf][kk + tg    ][c0 + g];
                bf[nt][1] = Bs[buf][kk + tg + 4][c0 + g];
            }
            #pragma unroll
            for (int mt = 0; mt < 2; mt++)
                #pragma unroll
                for (int nt = 0; nt < 4; nt++)
                    mma_tf32(acc[mt][nt], af[mt], bf[nt]);
        }
        if (nxt) { VST(buf ^ 1); __syncthreads(); }
        buf ^= 1;
    }
    #pragma unroll
    for (int mt = 0; mt < 2; mt++) {
        int r0 = bm + warpM * 32 + mt * 16 + g, r1 = r0 + 8;
        #pragma unroll
        for (int nt = 0; nt < 4; nt++) {
            int col = bn + warpN * 32 + nt * 8 + 2 * tg;
            atomicAdd(&C[(long)r0 * ldc + col], acc[mt][nt][0]);
            atomicAdd(&C[(long)r0 * ldc + col + 1], acc[mt][nt][1]);
            atomicAdd(&C[(long)r1 * ldc + col], acc[mt][nt][2]);
            atomicAdd(&C[(long)r1 * ldc + col + 1], acc[mt][nt][3]);
        }
    }
    #undef VLDG
    #undef VST
}

// ============ fused pinv megakernel: 24 GEMM stages, grid barrier ============
template<bool DIAG>
__device__ __forceinline__ void pinv_tile(
    const __half* __restrict__ A, const __half* __restrict__ B, __half* __restrict__ C,
    float alpha, float diagc, int bm, int bn,
    unsigned As[2][128][20], unsigned Bs[2][16][132])
{
    int tid = threadIdx.x, lane = tid & 31, wid = tid >> 5;
    int warpM = wid >> 1, warpN = wid & 1, g = lane >> 2, tg = lane & 3;
    int ar = tid >> 1, akb = (tid & 1) * 16;
    const __half* Ap = A + (long)(bm + ar) * NC + akb;
    int bp2 = tid >> 4, bsn = (tid & 15) * 8;
    const __half* Bp = B + (long)(2 * bp2) * NC + bn + bsn;
    __half dch = __float2half(diagc), zh = __float2half(0.f);

    unsigned aU[8], bU[8];
    float acc[2][8][4];
    #pragma unroll
    for (int i = 0; i < 2; i++)
        #pragma unroll
        for (int j = 0; j < 8; j++)
            #pragma unroll
            for (int l = 0; l < 4; l++) acc[i][j][l] = 0.f;

    #define HLDG(k0) do {                                                      \
        uint4 _a01 = __ldcg((const uint4*)(Ap + (k0)));                        \
        uint4 _a23 = __ldcg((const uint4*)(Ap + (k0) + 8));                    \
        aU[0]=_a01.x; aU[1]=_a01.y; aU[2]=_a01.z; aU[3]=_a01.w;                \
        aU[4]=_a23.x; aU[5]=_a23.y; aU[6]=_a23.z; aU[7]=_a23.w;                \
        uint4 _r0 = __ldcg((const uint4*)(Bp + (long)(k0) * NC));              \
        uint4 _r1 = __ldcg((const uint4*)(Bp + (long)(k0) * NC + NC));         \
        const unsigned short* _h0 = (const unsigned short*)&_r0;               \
        const unsigned short* _h1 = (const unsigned short*)&_r1;               \
        _Pragma("unroll")                                                      \
        for (int _j = 0; _j < 8; _j++)                                         \
            bU[_j] = (unsigned)_h0[_j] | ((unsigned)_h1[_j] << 16);            \
        if (DIAG) {                                                            \
            int _ka = (k0) + 2 * bp2, _kb = _ka + 1, _n = bn + bsn;            \
            _Pragma("unroll")                                                  \
            for (int _j = 0; _j < 8; _j++) {                                   \
                __half2 _d = __halves2half2((_ka == _n + _j) ? dch : zh,       \
                                            (_kb == _n + _j) ? dch : zh);      \
                __half2 _b = *(__half2*)&bU[_j];                               \
                __half2 _o = __hsub2(_d, _b);                                  \
                bU[_j] = *(unsigned*)&_o;                                      \
            }                                                                  \
        }                                                                      \
    } while (0)

    #define HST(p) do {                                                        \
        int _cb = (tid & 1) * 8;                                               \
        _Pragma("unroll")                                                      \
        for (int _j = 0; _j < 4; _j++)                                         \
            *(uint2*)&As[p][ar][_cb + 2 * _j] = make_uint2(aU[_j], aU[_j + 4]);\
        int _t = tid & 15;                                                     \
        _Pragma("unroll")                                                      \
        for (int _j = 0; _j < 8; _j++)                                         \
            Bs[p][bp2][_j * 16 + _t] = bU[_j];                                 \
    } while (0)

    HLDG(0); HST(0);
    __syncthreads();
    int buf = 0;
    for (int k0 = 0; k0 < NC; k0 += 32) {
        bool nxt = (k0 + 32) < NC;
        if (nxt) HLDG(k0 + 32);
        #pragma unroll
        for (int c = 0; c < 2; c++) {
            unsigned af[2][4];
            #pragma unroll
            for (int mt = 0; mt < 2; mt++) {
                int r0 = warpM * 32 + mt * 16;
                uint2 p0 = *(const uint2*)&As[buf][r0 + g    ][c * 8 + 2 * tg];
                uint2 p1 = *(const uint2*)&As[buf][r0 + g + 8][c * 8 + 2 * tg];
                af[mt][0] = p0.x; af[mt][1] = p1.x; af[mt][2] = p0.y; af[mt][3] = p1.y;
            }
            unsigned bf[8][2];
            {
                int s0 = g * 16 + warpN * 8;
                uint4 q0 = *(const uint4*)&Bs[buf][c * 8 + tg    ][s0];
                uint4 q1 = *(const uint4*)&Bs[buf][c * 8 + tg    ][s0 + 4];
                uint4 q2 = *(const uint4*)&Bs[buf][c * 8 + tg + 4][s0];
                uint4 q3 = *(const uint4*)&Bs[buf][c * 8 + tg + 4][s0 + 4];
                bf[0][0]=q0.x; bf[1][0]=q0.y; bf[2][0]=q0.z; bf[3][0]=q0.w;
                bf[4][0]=q1.x; bf[5][0]=q1.y; bf[6][0]=q1.z; bf[7][0]=q1.w;
                bf[0][1]=q2.x; bf[1][1]=q2.y; bf[2][1]=q2.z; bf[3][1]=q2.w;
                bf[4][1]=q3.x; bf[5][1]=q3.y; bf[6][1]=q3.z; bf[7][1]=q3.w;
            }
            #pragma unroll
            for (int mt = 0; mt < 2; mt++)
                #pragma unroll
                for (int nt = 0; nt < 8; nt++)
                    mma_f16(acc[mt][nt], af[mt], bf[nt]);
        }
        if (nxt) { HST(buf ^ 1); __syncthreads(); }
        buf ^= 1;
    }

    #pragma unroll
    for (int mt = 0; mt < 2; mt++) {
        int r0 = bm + warpM * 32 + mt * 16 + g, r1 = r0 + 8;
        #pragma unroll
        for (int nt = 0; nt < 8; nt++) {
            int col = bn + warpN * 64 + nt * 8 + 2 * tg;
            __stcg((unsigned*)&C[(long)r0 * NC + col],
                   f2h2(alpha * acc[mt][nt][0], alpha * acc[mt][nt][1]));
            __stcg((unsigned*)&C[(long)r1 * NC + col],
                   f2h2(alpha * acc[mt][nt][2], alpha * acc[mt][nt][3]));
        }
    }
    #undef HLDG
    #undef HST
}

__global__ void __launch_bounds__(256) pinv_fused_kernel(
    const __half* __restrict__ a2h, __half* __restrict__ xz,
    __half* __restrict__ u1, __half* __restrict__ u2,
    __half* __restrict__ za, __half* __restrict__ zb)
{
    __shared__ unsigned As[2][128][20];
    __shared__ unsigned Bs[2][16][132];
    int bid = blockIdx.x;
    int h = bid >> 4, by = (bid >> 2) & 3, bx = bid & 3;
    int bm = by * 128, bn = bx * 128;
    long off = (long)h * NC * NC;
    unsigned epoch = 0;

    #define GRID_BAR() do {                                                    \
        __threadfence();                                                       \
        __syncthreads();                                                       \
        if (threadIdx.x == 0) {                                                \
            atomicAdd(&g_bar, 1u);                                             \
            epoch += 128;                                                      \
            while (*(volatile unsigned*)&g_bar < epoch) { }                    \
            __threadfence();                                                   \
        }                                                                      \
        __syncthreads();                                                       \
    } while (0)

    __half* zc = za; __half* zn = zb;
    for (int it = 0; it < 6; it++) {
        pinv_tile<false>(a2h + off, zc + off, xz + off, 1.f, 0.f, bm, bn, As, Bs);
        GRID_BAR();
        pinv_tile<true >(xz + off, xz + off, u1 + off, 1.f, 7.f, bm, bn, As, Bs);
        GRID_BAR();
        pinv_tile<true >(xz + off, u1 + off, u2 + off, 1.f, 15.f, bm, bn, As, Bs);
        GRID_BAR();
        pinv_tile<true >(zc + off, u2 + off, zn + off, 0.25f, 13.f, bm, bn, As, Bs);
        if (it != 5) GRID_BAR();
        __half* t = zc; zc = zn; zn = t;
    }
    #undef GRID_BAR
}

// ---------------- sort ----------------
__global__ void init_scalars_kernel() { g_maxcs = 0u; }

__global__ void hist_kernel(const int* __restrict__ labels) {
    __shared__ int sh[NC];
    int t = threadIdx.x;
    sh[t] = 0; sh[t + 256] = 0;
    __syncthreads();
    atomicAdd(&sh[labels[blockIdx.x * 256 + t]], 1);
    __syncthreads();
    g_bh[blockIdx.x * NC + t]       = sh[t];
    g_bh[blockIdx.x * NC + t + 256] = sh[t + 256];
}

__global__ void scan_kernel() {
    __shared__ int s[NC];
    int c = threadIdx.x;
    int tot = 0;
    for (int b = 0; b < 64; b++) { int v = g_bh[b * NC + c]; g_bh[b * NC + c] = tot; tot += v; }
    g_counts[c] = tot; s[c] = tot;
    __syncthreads();
    for (int d = 1; d < NC; d <<= 1) {
        int v = (c >= d) ? s[c - d] : 0;
        __syncthreads(); s[c] += v; __syncthreads();
    }
    int excl = s[c] - tot;
    g_offsets[c] = excl;
    for (int b = 0; b < 64; b++) g_bh[b * NC + c] += excl;
}

__global__ void place_kernel(const int* __restrict__ labels) {
    __shared__ int slab[256];
    int t = threadIdx.x, i = blockIdx.x * 256 + t;
    int c = labels[i];
    slab[t] = c;
    __syncthreads();
    int rank = 0;
    for (int j = 0; j < t; j++) rank += (slab[j] == c);
    g_idx[g_bh[blockIdx.x * NC + c] + rank] = i;
}

__global__ void landmark_kernel() {
    int c = blockIdx.x, h = blockIdx.y, t = threadIdx.x;
    int start = g_offsets[c], cnt = g_counts[c];
    int col = (t < DH) ? (h * DH + t) : (DIM + h * DH + (t - DH));
    float s = 0.f;
    for (int r = 0; r < cnt; r++) s += g_qkv[(long)(start + r) * QKVW + col];
    float m = s / (float)(cnt > 0 ? cnt : 1);
    long o = ((long)h * NC + c) * DH;
    if (t < DH) g_ql[o + t] = m; else g_kl[o + (t - DH)] = m;
}

__global__ void softmax_kernel(float* __restrict__ d, int C) {
    d += blockIdx.x * (long)C;
    __shared__ float red[256];
    int t = threadIdx.x;
    float m = -1e30f;
    for (int i = t; i < C; i += 256) m = fmaxf(m, d[i]);
    red[t] = m; __syncthreads();
    for (int s = 128; s > 0; s >>= 1) { if (t < s) red[t] = fmaxf(red[t], red[t + s]); __syncthreads(); }
    m = red[0]; __syncthreads();
    float sum = 0.f;
    for (int i = t; i < C; i += 256) { float e = expf(d[i] - m); d[i] = e; sum += e; }
    red[t] = sum; __syncthreads();
    for (int s = 128; s > 0; s >>= 1) { if (t < s) red[t] += red[t + s]; __syncthreads(); }
    float inv = 1.f / red[0];
    for (int i = t; i < C; i += 256) d[i] *= inv;
}

// stats over half matrix rows
__global__ void stats_h_kernel(const __half* __restrict__ d, float2* __restrict__ st, int C) {
    long row = blockIdx.x;
    const __half2* d2 = (const __half2*)(d + row * (long)C);
    int C2 = C / 2;
    __shared__ float red[256];
    int t = threadIdx.x;
    float m = -1e30f;
    for (int i = t; i < C2; i += 256) {
        float2 v = __half22float2(d2[i]);
        m = fmaxf(m, fmaxf(v.x, v.y));
    }
    red[t] = m; __syncthreads();
    for (int s = 128; s > 0; s >>= 1) { if (t < s) red[t] = fmaxf(red[t], red[t + s]); __syncthreads(); }
    m = red[0]; __syncthreads();
    float sum = 0.f;
    for (int i = t; i < C2; i += 256) {
        float2 v = __half22float2(d2[i]);
        sum += __expf(v.x - m) + __expf(v.y - m);
    }
    red[t] = sum; __syncthreads();
    for (int s = 128; s > 0; s >>= 1) { if (t < s) red[t] += red[t + s]; __syncthreads(); }
    if (t == 0) st[row] = make_float2(m, 1.f / red[0]);
}

__global__ void colsum_kernel() {
    int h = blockIdx.x, t = threadIdx.x;
    const float* d = g_a2 + (long)h * NC * NC;
    float s0 = 0.f, s1 = 0.f, s2 = 0.f, s3 = 0.f;
    #pragma unroll 4
    for (int r = 0; r < NC; r += 4) {
        s0 += d[(long)r * NC + t];
        s1 += d[(long)(r + 1) * NC + t];
        s2 += d[(long)(r + 2) * NC + t];
        s3 += d[(long)(r + 3) * NC + t];
    }
    float s = (s0 + s1) + (s2 + s3);
    __shared__ float red[512];
    red[t] = s; __syncthreads();
    for (int k = 256; k > 0; k >>= 1) { if (t < k) red[t] = fmaxf(red[t], red[t + k]); __syncthreads(); }
    if (t == 0) atomicMax(&g_maxcs, __float_as_uint(red[0]));
}

__global__ void zinit_kernel() {
    if (blockIdx.x == 0 && threadIdx.x == 0) g_bar = 0u;
    float scale = 1.f / __uint_as_float(g_maxcs);
    long id = (long)blockIdx.x * 256 + threadIdx.x;
    int j = (int)(id & 511), i = (int)((id >> 9) & 511);
    long h = id >> 18;
    g_za[id]  = __float2half(g_a2[(h << 18) + ((long)j << 9) + i] * scale);
    g_a2h[id] = __float2half(g_a2[id]);
}

__global__ void zero_kernel(float* __restrict__ p) {
    p[(long)blockIdx.x * 256 + threadIdx.x] = 0.f;
}

// depthwise conv residual -> PURE STORE into osort (flash1 accumulates on top)
#define CTI 128
__global__ void conv_add_kernel(const float* __restrict__ w_res) {
    __shared__ float sv[CTI + KW - 1][DH];
    __shared__ float w[KW];
    int h = blockIdx.y, i0 = blockIdx.x * CTI, t = threadIdx.x;
    if (t < KW) w[t] = w_res[h * KW + t];
    for (int e = t; e < (CTI + KW - 1) * (DH / 2); e += 256) {
        int r = e >> 5, c2 = e & 31;
        int gi = i0 + r - KW / 2;
        float2 v = make_float2(0.f, 0.f);
        if (gi >= 0 && gi < N_TOK)
            v = *(const float2*)&g_qkv[(long)gi * QKVW + 2 * DIM + h * DH + c2 * 2];
        *(float2*)&sv[r][c2 * 2] = v;
    }
    __syncthreads();
    for (int e = t; e < CTI * (DH / 2); e += 256) {
        int r = e >> 5, c2 = e & 31;
        float2 acc = make_float2(0.f, 0.f);
        #pragma unroll
        for (int k = 0; k < KW; k++) {
            float2 v = *(float2*)&sv[r + k][c2 * 2];
            acc.x += w[k] * v.x; acc.y += w[k] * v.y;
        }
        *(float2*)&g_osort[(long)(i0 + r) * DIM + h * DH + c2 * 2] = acc;
    }
}

// flash1: osort += softmax(q @ kl^T) @ wm (fp16 MMAs, register P)
__global__ void __launch_bounds__(128) flash1_kernel() {
    __shared__ unsigned Ks[64][36];
    __shared__ unsigned Ws[64][36];
    int h = blockIdx.y, bm = blockIdx.x * 64;
    int tid = threadIdx.x, lane = tid & 31, wid = tid >> 5;
    int g = lane >> 2, tg = lane & 3, wr0 = wid * 16;

    for (int e = tid; e < 64 * 8; e += 128) {
        int r = e >> 3, d8 = (e & 7) * 8;
        const float* q = &g_qkv[(long)(bm + r) * QKVW + h * DH + d8];
        float4 v0 = *(const float4*)q, v1 = *(const float4*)(q + 4);
        int c2 = d8 >> 1;
        Ks[r][c2]     = f2h2(v0.x, v0.y);
        Ks[r][c2 + 1] = f2h2(v0.z, v0.w);
        Ks[r][c2 + 2] = f2h2(v1.x, v1.y);
        Ks[r][c2 + 3] = f2h2(v1.z, v1.w);
    }
    __syncthreads();
    unsigned qf[4][4];
    #pragma unroll
    for (int c = 0; c < 4; c++) {
        qf[c][0] = Ks[wr0 + g    ][c * 8 + tg];
        qf[c][1] = Ks[wr0 + g + 8][c * 8 + tg];
        qf[c][2] = Ks[wr0 + g    ][c * 8 + tg + 4];
        qf[c][3] = Ks[wr0 + g + 8][c * 8 + tg + 4];
    }

    float m0 = -1e30f, m1 = -1e30f, l0 = 0.f, l1 = 0.f;
    float O[8][4] = {};
    const float* klb = g_kl + (long)h * NC * DH;
    const float* wmb = g_wm + (long)h * NC * DH;

    for (int jc = 0; jc < NC; jc += 64) {
        __syncthreads();
        for (int e = tid; e < 64 * 8; e += 128) {
            int n = e >> 3, d8 = (e & 7) * 8;
            const float* kp = &klb[(long)(jc + n) * DH + d8];
            float4 v0 = *(const float4*)kp, v1 = *(const float4*)(kp + 4);
            int c2 = d8 >> 1;
            Ks[n][c2]     = f2h2(v0.x, v0.y);
            Ks[n][c2 + 1] = f2h2(v0.z, v0.w);
            Ks[n][c2 + 2] = f2h2(v1.x, v1.y);
            Ks[n][c2 + 3] = f2h2(v1.z, v1.w);
        }
        for (int e = tid; e < 32 * 16; e += 128) {
            int j2 = e >> 4, d4 = (e & 15) * 4;
            const float* w0 = &wmb[(long)(jc + 2 * j2) * DH + d4];
            const float* w1 = w0 + DH;
            float4 a = *(const float4*)w0, b = *(const float4*)w1;
            Ws[d4 + 0][j2] = f2h2(a.x, b.x);
            Ws[d4 + 1][j2] = f2h2(a.y, b.y);
            Ws[d4 + 2][j2] = f2h2(a.z, b.z);
            Ws[d4 + 3][j2] = f2h2(a.w, b.w);
        }
        __syncthreads();

        float s[8][4] = {};
        #pragma unroll
        for (int c = 0; c < 4; c++) {
            #pragma unroll
            for (int nt = 0; nt < 8; nt++) {
                unsigned bf[2];
                bf[0] = Ks[nt * 8 + g][c * 8 + tg];
                bf[1] = Ks[nt * 8 + g][c * 8 + tg + 4];
                mma_f16(s[nt], qf[c], bf);
            }
        }

        float mc0 = -1e30f, mc1 = -1e30f;
        #pragma unroll
        for (int nt = 0; nt < 8; nt++) {
            mc0 = fmaxf(mc0, fmaxf(s[nt][0], s[nt][1]));
            mc1 = fmaxf(mc1, fmaxf(s[nt][2], s[nt][3]));
        }
        mc0 = fmaxf(mc0, __shfl_xor_sync(~0u, mc0, 1));
        mc0 = fmaxf(mc0, __shfl_xor_sync(~0u, mc0, 2));
        mc1 = fmaxf(mc1, __shfl_xor_sync(~0u, mc1, 1));
        mc1 = fmaxf(mc1, __shfl_xor_sync(~0u, mc1, 2));
        float mn0 = fmaxf(m0, mc0), mn1 = fmaxf(m1, mc1);
        float sc0 = __expf(m0 - mn0), sc1 = __expf(m1 - mn1);
        float ps0 = 0.f, ps1 = 0.f;
        float p[8][4];
        #pragma unroll
        for (int nt = 0; nt < 8; nt++) {
            p[nt][0] = __expf(s[nt][0] - mn0);
            p[nt][1] = __expf(s[nt][1] - mn0);
            p[nt][2] = __expf(s[nt][2] - mn1);
            p[nt][3] = __expf(s[nt][3] - mn1);
            ps0 += p[nt][0] + p[nt][1];
            ps1 += p[nt][2] + p[nt][3];
            O[nt][0] *= sc0; O[nt][1] *= sc0; O[nt][2] *= sc1; O[nt][3] *= sc1;
        }
        ps0 += __shfl_xor_sync(~0u, ps0, 1); ps0 += __shfl_xor_sync(~0u, ps0, 2);
        ps1 += __shfl_xor_sync(~0u, ps1, 1); ps1 += __shfl_xor_sync(~0u, ps1, 2);
        l0 = l0 * sc0 + ps0; l1 = l1 * sc1 + ps1;
        m0 = mn0; m1 = mn1;

        unsigned pf[4][4];
        #pragma unroll
        for (int c = 0; c < 4; c++) {
            pf[c][0] = f2h2(p[2*c][0],   p[2*c][1]);
            pf[c][1] = f2h2(p[2*c][2],   p[2*c][3]);
            pf[c][2] = f2h2(p[2*c+1][0], p[2*c+1][1]);
            pf[c][3] = f2h2(p[2*c+1][2], p[2*c+1][3]);
        }
        #pragma unroll
        for (int c = 0; c < 4; c++) {
            #pragma unroll
            for (int nt = 0; nt < 8; nt++) {
                unsigned bf[2];
                bf[0] = Ws[nt * 8 + g][c * 8 + tg];
                bf[1] = Ws[nt * 8 + g][c * 8 + tg + 4];
                mma_f16(O[nt], pf[c], bf);
            }
        }
    }

    float inv0 = 1.f / l0, inv1 = 1.f / l1;
    int r0 = bm + wr0 + g, r1 = r0 + 8;
    #pragma unroll
    for (int nt = 0; nt < 8; nt++) {
        int col = h * DH + nt * 8 + 2 * tg;
        float2* o0 = (float2*)&g_osort[(long)r0 * DIM + col];
        float2* o1 = (float2*)&g_osort[(long)r1 * DIM + col];
        float2 c0 = *o0, c1 = *o1;
        *o0 = make_float2(c0.x + O[nt][0] * inv0, c0.y + O[nt][1] * inv0);
        *o1 = make_float2(c1.x + O[nt][2] * inv1, c1.y + O[nt][3] * inv1);
    }
}

// ---------------- small GEMM (wm = z @ a3v): half A, fp32 B/C, tf32 MMA, 128 thr ----------------
__global__ void __launch_bounds__(128) small_gemm_kernel(
    const __half* __restrict__ A, int lda, long sA,
    const float* __restrict__ B, int ldb, long sB,
    float* __restrict__ C, int ldc, long sC, int K)
{
    __shared__ unsigned As[2][64][20];
    __shared__ unsigned Bs[2][16][72];
    int z = blockIdx.z;
    A += (long)z * sA; B += (long)z * sB; C += (long)z * sC;
    int bm = blockIdx.y * 64, bn = blockIdx.x * 64;
    int tid = threadIdx.x, lane = tid & 31, wid = tid >> 5;
    int warpM = wid >> 1, warpN = wid & 1, g = lane >> 2, tg = lane & 3;
    int ar = tid >> 1, ak = (tid & 1) * 8;
    const __half* Ap = A + (long)(bm + ar) * lda + ak;
    int bk = tid >> 4, bnn = (tid & 15) * 4;
    const float* Bp = B + (long)bk * ldb + bn + bnn;
    float aR[8], bR[8];
    float acc[2][4][4] = {};

    #define SLDG(k0) do {                                                      \
        uint4 _av = __ldcg((const uint4*)(Ap + (k0)));                         \
        const __half* _ah = (const __half*)&_av;                               \
        _Pragma("unroll")                                                      \
        for (int _i = 0; _i < 8; _i++) aR[_i] = __half2float(_ah[_i]);         \
        float4 _b0 = *(const float4*)(Bp + (long)(k0) * ldb);                  \
        float4 _b1 = *(const float4*)(Bp + (long)((k0) + 8) * ldb);            \
        bR[0]=_b0.x; bR[1]=_b0.y; bR[2]=_b0.z; bR[3]=_b0.w;                    \
        bR[4]=_b1.x; bR[5]=_b1.y; bR[6]=_b1.z; bR[7]=_b1.w;                    \
    } while (0)
    #define SST(p) do {                                                        \
        _Pragma("unroll")                                                      \
        for (int _i = 0; _i < 8; _i++) As[p][ar][ak + _i] = f2tf32(aR[_i]);    \
        _Pragma("unroll")                                                      \
        for (int _i = 0; _i < 4; _i++) {                                       \
            Bs[p][bk][bnn + _i] = f2tf32(bR[_i]);                              \
            Bs[p][bk + 8][bnn + _i] = f2tf32(bR[4 + _i]);                      \
        }                                                                      \
    } while (0)

    SLDG(0); SST(0);
    __syncthreads();
    int buf = 0;
    for (int k0 = 0; k0 < K; k0 += 16) {
        bool nxt = (k0 + 16) < K;
        if (nxt) SLDG(k0 + 16);
        #pragma unroll
        for (int kk = 0; kk < 16; kk += 8) {
            unsigned af[2][4];
            #pragma unroll
            for (int mt = 0; mt < 2; mt++) {
                int r0 = warpM * 32 + mt * 16;
                af[mt][0] = As[buf][r0 + g    ][kk + tg];
                af[mt][1] = As[buf][r0 + g + 8][kk + tg];
                af[mt][2] = As[buf][r0 + g    ][kk + tg + 4];
                af[mt][3] = As[buf][r0 + g + 8][kk + tg + 4];
            }
            unsigned bf[4][2];
            #pragma unroll
            for (int nt = 0; nt < 4; nt++) {
                int c0 = warpN * 32 + nt * 8;
                bf[nt][0] = Bs[buf][kk + tg    ][c0 + g];
                bf[nt][1] = Bs[buf][kk + tg + 4][c0 + g];
            }
            #pragma unroll
            for (int mt = 0; mt < 2; mt++)
                #pragma unroll
                for (int nt = 0; nt < 4; nt++)
                    mma_tf32(acc[mt][nt], af[mt], bf[nt]);
        }
        if (nxt) { SST(buf ^ 1); __syncthreads(); }
        buf ^= 1;
    }
    #pragma unroll
    for (int mt = 0; mt < 2; mt++) {
        int r0 = bm + warpM * 32 + mt * 16 + g, r1 = r0 + 8;
        #pragma unroll
        for (int nt = 0; nt < 4; nt++) {
            int col = bn + warpN * 32 + nt * 8 + 2 * tg;
            *(float2*)&C[(long)r0 * ldc + col] = make_float2(acc[mt][nt][0], acc[mt][nt][1]);
            *(float2*)&C[(long)r1 * ldc + col] = make_float2(acc[mt][nt][2], acc[mt][nt][3]);
        }
    }
    #undef SLDG
    #undef SST
}

// ---------------- BM=128 tf32 GEMM (a2 only: ql @ kl^T) ----------------
__global__ void __launch_bounds__(256) a2_gemm_kernel(
    const float* __restrict__ A, const float* __restrict__ B, float* __restrict__ C)
{
    __shared__ unsigned As[2][128][20];
    __shared__ unsigned Bs[2][16][136];
    long SL = (long)NC * DH, S2 = (long)NC * NC;
    int batch = blockIdx.z;
    A += batch * SL; B += batch * SL; C += batch * S2;
    int bm = blockIdx.y * 128, bn = blockIdx.x * 128;
    int tid = threadIdx.x, lane = tid & 31, wid = tid >> 5;
    int warpM = wid >> 1, warpN = wid & 1, g = lane >> 2, tg = lane & 3;
    int ar = tid >> 1, ak = (tid & 1) * 8;
    const float* Ap = A + (long)(bm + ar) * DH + ak;
    int bnn = tid >> 1, bk = (tid & 1) * 8;
    const float* Bp = B + (long)(bn + bnn) * DH + bk;
    float aR[8], bR[8];
    float acc[2][8][4];
    #pragma unroll
    for (int i = 0; i < 2; i++)
        #pragma unroll
        for (int j = 0; j < 8; j++)
            #pragma unroll
            for (int l = 0; l < 4; l++) acc[i][j][l] = 0.f;

    #define ALDG(k0) do {                                                      \
        float4 _a0 = *(const float4*)(Ap + (k0));                              \
        float4 _a1 = *(const float4*)(Ap + (k0) + 4);                          \
        aR[0]=_a0.x; aR[1]=_a0.y; aR[2]=_a0.z; aR[3]=_a0.w;                    \
        aR[4]=_a1.x; aR[5]=_a1.y; aR[6]=_a1.z; aR[7]=_a1.w;                    \
        float4 _b0 = *(const float4*)(Bp + (k0));                              \
        float4 _b1 = *(const float4*)(Bp + (k0) + 4);                          \
        bR[0]=_b0.x; bR[1]=_b0.y; bR[2]=_b0.z; bR[3]=_b0.w;                    \
        bR[4]=_b1.x; bR[5]=_b1.y; bR[6]=_b1.z; bR[7]=_b1.w;                    \
    } while (0)
    #define AST(p) do {                                                        \
        _Pragma("unroll")                                                      \
        for (int _i = 0; _i < 8; _i++) As[p][ar][ak + _i] = f2tf32(aR[_i]);    \
        _Pragma("unroll")                                                      \
        for (int _i = 0; _i < 8; _i++) Bs[p][bk + _i][bnn] = f2tf32(bR[_i]);   \
    } while (0)

    ALDG(0); AST(0);
    __syncthreads();
    int buf = 0;
    for (int k0 = 0; k0 < DH; k0 += 16) {
        bool nxt = (k0 + 16) < DH;
        if (nxt) ALDG(k0 + 16);
        #pragma unroll
        for (int kk = 0; kk < 16; kk += 8) {
            unsigned af[2][4];
            #pragma unroll
            for (int mt = 0; mt < 2; mt++) {
                int r0 = warpM * 32 + mt * 16;
                af[mt][0] = As[buf][r0 + g    ][kk + tg];
                af[mt][1] = As[buf][r0 + g + 8][kk + tg];
                af[mt][2] = As[buf][r0 + g    ][kk + tg + 4];
                af[mt][3] = As[buf][r0 + g + 8][kk + tg + 4];
            }
            unsigned bf[8][2];
            #pragma unroll
            for (int nt = 0; nt < 8; nt++) {
                int c0 = warpN * 64 + nt * 8;
                bf[nt][0] = Bs[buf][kk + tg    ][c0 + g];
                bf[nt][1] = Bs[buf][kk + tg + 4][c0 + g];
            }
            #pragma unroll
            for (int mt = 0; mt < 2; mt++)
                #pragma unroll
                for (int nt = 0; nt < 8; nt++)
                    mma_tf32(acc[mt][nt], af[mt], bf[nt]);
        }
        if (nxt) { AST(buf ^ 1); __syncthreads(); }
        buf ^= 1;
    }
    #pragma unroll
    for (int mt = 0; mt < 2; mt++) {
        int r0 = bm + warpM * 32 + mt * 16 + g, r1 = r0 + 8;
        #pragma unroll
        for (int nt = 0; nt < 8; nt++) {
            int col = bn + warpN * 64 + nt * 8 + 2 * tg;
            *(float2*)&C[(long)r0 * NC + col] = make_float2(acc[mt][nt][0], acc[mt][nt][1]);
            *(float2*)&C[(long)r1 * NC + col] = make_float2(acc[mt][nt][2], acc[mt][nt][3]);
        }
    }
    #undef ALDG
    #undef AST
}

extern "C" void kernel_launch(void* const* d_in, const int* in_sizes, int n_in,
                              void* d_out, int out_size)
{
    const float* x      = (const float*)d_in[0];
    const int*   labels = (const int*)  d_in[1];
    const float* w_qkv  = (const float*)d_in[2];
    const float* w_res  = (const float*)d_in[3];
    const float* w_out  = (const float*)d_in[4];
    const float* b_out  = (const float*)d_in[5];
    float* out = (float*)d_out;

    float *qkv, *a2, *ql, *kl, *a3v, *wm, *osort;
    __half *sim3, *a2h, *xz, *u1, *u2, *za, *zb;
    float2 *st3;
    int* idx;
    cudaGetSymbolAddress((void**)&qkv,  g_qkv);
    cudaGetSymbolAddress((void**)&sim3, g_sim3);
    cudaGetSymbolAddress((void**)&a2,   g_a2);
    cudaGetSymbolAddress((void**)&a2h,  g_a2h);
    cudaGetSymbolAddress((void**)&xz,   g_xz);
    cudaGetSymbolAddress((void**)&u1,   g_u1);
    cudaGetSymbolAddress((void**)&u2,   g_u2);
    cudaGetSymbolAddress((void**)&za,   g_za);
    cudaGetSymbolAddress((void**)&zb,   g_zb);
    cudaGetSymbolAddress((void**)&ql,   g_ql);
    cudaGetSymbolAddress((void**)&kl,   g_kl);
    cudaGetSymbolAddress((void**)&a3v,  g_a3v);
    cudaGetSymbolAddress((void**)&wm,   g_wm);
    cudaGetSymbolAddress((void**)&osort,g_osort);
    cudaGetSymbolAddress((void**)&st3,  g_st3);
    cudaGetSymbolAddress((void**)&idx,  g_idx);

    static cudaStream_t s2 = nullptr;
    static cudaEvent_t evS = nullptr, evK = nullptr, evL = nullptr, evJ = nullptr;
    if (!s2) {
        cudaStreamCreateWithFlags(&s2, cudaStreamNonBlocking);
        cudaEventCreateWithFlags(&evS, cudaEventDisableTiming);
        cudaEventCreateWithFlags(&evK, cudaEventDisableTiming);
        cudaEventCreateWithFlags(&evL, cudaEventDisableTiming);
        cudaEventCreateWithFlags(&evJ, cudaEventDisableTiming);
    }

    const long S2 = (long)NC * NC;
    const long SL = (long)NC * DH;
    const long ST3 = (long)NC * N_TOK;   // half elements per head

    // sort
    init_scalars_kernel<<<1, 1>>>();
    hist_kernel <<<64, 256>>>(labels);
    scan_kernel <<<1, 512>>>();
    place_kernel<<<64, 256>>>(labels);
    cudaEventRecord(evS, 0);

    // balanced pre-landmark split: q on main, k on s2 (both 8.6 GF)
    tt_gemm<true, false, false><<<dim3(512 / 128, N_TOK / 128, 1), 256>>>(
        x, DIM, 0, w_qkv, DIM, 0, qkv, QKVW, 0, DIM, 1.f, idx, nullptr, nullptr);

    cudaStreamWaitEvent(s2, evS, 0);
    tt_gemm<true, false, false><<<dim3(512 / 128, N_TOK / 128, 1), 256, 0, s2>>>(
        x, DIM, 0, w_qkv + (long)512 * DIM, DIM, 0, qkv + 512, QKVW, 0,
        DIM, 1.f, idx, nullptr, nullptr);
    cudaEventRecord(evK, s2);

    // v GEMM on s2 (overlaps main's landmark + a2 path)
    tt_gemm<true, false, false><<<dim3(512 / 128, N_TOK / 128, 1), 256, 0, s2>>>(
        x, DIM, 0, w_qkv + (long)1024 * DIM, DIM, 0, qkv + 1024, QKVW, 0,
        DIM, 1.f, idx, nullptr, nullptr);

    // main: wait for k, then landmarks
    cudaStreamWaitEvent(0, evK, 0);
    landmark_kernel<<<dim3(NC, NH), 128>>>();
    cudaEventRecord(evL, 0);

    // --- s2 branch: sim3 (half) -> stats -> a3v -> conv ---
    cudaStreamWaitEvent(s2, evL, 0);
    tt_gemm<true, false, true><<<dim3(N_TOK / 128, NC / 128, NH), 256, 0, s2>>>(
        ql, DH, SL, qkv + DIM, QKVW, 64, (float*)sim3, N_TOK, ST3 / 2, DH, 1.f,
        nullptr, nullptr, nullptr);
    stats_h_kernel<<<NH * NC, 256, 0, s2>>>(sim3, st3, N_TOK);
    zero_kernel<<<(NH * NC * DH) / 256, 256, 0, s2>>>(a3v);
    a3v_gemm_kernel<<<dim3(DH / 64, NC / 128, NH * 8), 256, 0, s2>>>(
        sim3, N_TOK, ST3, qkv + 2 * DIM, QKVW, 64, a3v, DH, SL, N_TOK, 8, st3, NC);
    conv_add_kernel<<<dim3(N_TOK / CTI, NH), 256, 0, s2>>>(w_res);
    cudaEventRecord(evJ, s2);

    // --- main branch: a2 + fused pinv ---
    a2_gemm_kernel<<<dim3(NC / 128, NC / 128, NH), 256>>>(ql, kl, a2);
    softmax_kernel<<<NH * NC, 256>>>(a2, NC);
    colsum_kernel<<<NH, 512>>>();
    zinit_kernel<<<(NH * NC * NC) / 256, 256>>>();

    pinv_fused_kernel<<<128, 256>>>(a2h, xz, u1, u2, za, zb);

    // join: wm needs a3v (s2); flash1 needs conv-written osort (s2)
    cudaStreamWaitEvent(0, evJ, 0);
    small_gemm_kernel<<<dim3(1, NC / 64, NH), 128>>>(za, NC, S2, a3v, DH, SL, wm, DH, SL, NC);

    flash1_kernel<<<dim3(N_TOK / 64, NH), 128>>>();

    // output projection + bias + scatter
    tt_gemm<true, true, false><<<dim3(DIM / 128, N_TOK / 128, 1), 256>>>(
        osort, DIM, 0, w_out, DIM, 0, out, DIM, 0, DIM, 1.f, nullptr, idx, b_out);
}